// round 1
// baseline (speedup 1.0000x reference)
#include <cuda_runtime.h>
#include <cuda_bf16.h>
#include <math.h>

// ---------------- problem constants ----------------
#define S     2048
#define HID   2560
#define NH    8
#define NKV   4
#define DH    256
#define WIN   1024
#define QN    (NH*DH)    // 2048
#define KVN   (NKV*DH)   // 1024

// ---------------- scratch (static device memory; no runtime allocs) ----------------
__device__ float g_q[S * QN];     // 16 MB
__device__ float g_k[S * KVN];    // 8 MB
__device__ float g_v[S * KVN];    // 8 MB
__device__ float g_attn[S * QN];  // 16 MB

// =====================================================================
// SGEMM: C[M,N] = A[M,K] @ B[K,N], all row-major fp32.
// 128x128 block tile, K-tile 16, 256 threads, 8x8 per thread (4+4 split).
// All dims here are multiples of the tile sizes (2048/1024/2560/2048).
// =====================================================================
__global__ __launch_bounds__(256) void sgemm_kernel(
    const float* __restrict__ A, const float* __restrict__ B,
    float* __restrict__ C, int M, int N, int K)
{
    __shared__ float As[16][132];   // transposed A tile: As[k][m]
    __shared__ float Bs[16][132];   // Bs[k][n]

    const int t  = threadIdx.x;
    const int tx = t & 15;
    const int ty = t >> 4;
    const int m0 = blockIdx.y * 128;
    const int n0 = blockIdx.x * 128;

    const int ar0 = ty * 4;        // rows ar0..+3 and ar0+64..+67
    const int bc0 = tx * 4;        // cols bc0..+3 and bc0+64..+67

    float acc[8][8];
#pragma unroll
    for (int i = 0; i < 8; i++)
#pragma unroll
        for (int j = 0; j < 8; j++) acc[i][j] = 0.f;

    for (int k0 = 0; k0 < K; k0 += 16) {
        // load A tile 128x16 (transposed into As)
#pragma unroll
        for (int p = 0; p < 2; p++) {
            int fid = t + p * 256;
            int row = fid >> 2;               // 0..127
            int kf  = (fid & 3) * 4;
            float4 v = *(const float4*)(A + (size_t)(m0 + row) * K + k0 + kf);
            As[kf + 0][row] = v.x;
            As[kf + 1][row] = v.y;
            As[kf + 2][row] = v.z;
            As[kf + 3][row] = v.w;
        }
        // load B tile 16x128
#pragma unroll
        for (int p = 0; p < 2; p++) {
            int fid = t + p * 256;
            int kr  = fid >> 5;               // 0..15
            int c4  = (fid & 31) * 4;
            float4 v = *(const float4*)(B + (size_t)(k0 + kr) * N + n0 + c4);
            *(float4*)&Bs[kr][c4] = v;
        }
        __syncthreads();

#pragma unroll
        for (int kk = 0; kk < 16; kk++) {
            float a[8], b[8];
            *(float4*)&a[0] = *(const float4*)&As[kk][ar0];
            *(float4*)&a[4] = *(const float4*)&As[kk][ar0 + 64];
            *(float4*)&b[0] = *(const float4*)&Bs[kk][bc0];
            *(float4*)&b[4] = *(const float4*)&Bs[kk][bc0 + 64];
#pragma unroll
            for (int i = 0; i < 8; i++)
#pragma unroll
                for (int j = 0; j < 8; j++)
                    acc[i][j] = fmaf(a[i], b[j], acc[i][j]);
        }
        __syncthreads();
    }

#pragma unroll
    for (int i = 0; i < 8; i++) {
        int row = (i < 4) ? (ar0 + i) : (ar0 + 64 + (i - 4));
        float* crow = C + (size_t)(m0 + row) * N + n0;
        float4 v0 = make_float4(acc[i][0], acc[i][1], acc[i][2], acc[i][3]);
        float4 v1 = make_float4(acc[i][4], acc[i][5], acc[i][6], acc[i][7]);
        *(float4*)(crow + bc0)      = v0;
        *(float4*)(crow + bc0 + 64) = v1;
    }
}

// =====================================================================
// Fused RMSNorm (+ optional weight) + RoPE, in place.
// grid (S, 16): idx<8 -> q head, idx<12 -> k head, else v head (no rope).
// =====================================================================
__global__ __launch_bounds__(256) void norm_rope_kernel(
    float* __restrict__ q, float* __restrict__ k, float* __restrict__ v,
    const float* __restrict__ cosp, const float* __restrict__ sinp,
    const float* __restrict__ qw, const float* __restrict__ kw)
{
    const int s   = blockIdx.x;
    const int idx = blockIdx.y;
    const int d   = threadIdx.x;        // 0..255

    float* base;
    const float* w;
    bool rope;
    if (idx < 8)       { base = q + (size_t)s * QN  + idx * DH;        w = qw;      rope = true;  }
    else if (idx < 12) { base = k + (size_t)s * KVN + (idx - 8) * DH;  w = kw;      rope = true;  }
    else               { base = v + (size_t)s * KVN + (idx - 12) * DH; w = nullptr; rope = false; }

    float x = base[d];
    float ss = x * x;
#pragma unroll
    for (int o = 16; o; o >>= 1) ss += __shfl_xor_sync(0xffffffffu, ss, o);

    __shared__ float wsum[8];
    if ((d & 31) == 0) wsum[d >> 5] = ss;
    __syncthreads();
    float tot = 0.f;
#pragma unroll
    for (int i = 0; i < 8; i++) tot += wsum[i];

    float inv = rsqrtf(tot * (1.0f / 256.0f) + 1e-6f);
    float y = x * inv;
    if (w) y *= w[d];

    __shared__ float sh[256];
    sh[d] = y;
    __syncthreads();

    float out = y;
    if (rope) {
        float c  = cosp[(size_t)s * DH + d];
        float si = sinp[(size_t)s * DH + d];
        float rh = (d < 128) ? -sh[d + 128] : sh[d - 128];
        out = y * c + rh * si;
    }
    base[d] = out;
}

// =====================================================================
// Flash-style fp32 attention with sliding-window causal mask.
// CTA = (64-query tile, head). 64-key blocks. Online softmax.
// smem: Qs[64][257], Ks[64][257], Vs[64][260], Ss[64][65], m/l/corr[64]
// =====================================================================
#define ATT_SMEM_FLOATS (64*257 + 64*257 + 64*260 + 64*65 + 3*64)
#define ATT_SMEM_BYTES  (ATT_SMEM_FLOATS * 4)

__global__ __launch_bounds__(256) void attn_kernel(
    const float* __restrict__ Q, const float* __restrict__ K,
    const float* __restrict__ V, float* __restrict__ O)
{
    extern __shared__ float sm[];
    float* Qs   = sm;                     // [64][257]
    float* Ks   = Qs + 64 * 257;          // [64][257]
    float* Vs   = Ks + 64 * 257;          // [64][260]
    float* Ss   = Vs + 64 * 260;          // [64][65]
    float* mrow = Ss + 64 * 65;           // [64]
    float* lrow = mrow + 64;              // [64]
    float* crow = lrow + 64;              // [64]

    const int t  = threadIdx.x;
    const int tx = t & 15;
    const int ty = t >> 4;
    const int q0 = blockIdx.x * 64;
    const int h  = blockIdx.y;
    const int kvh = h >> 1;               // GQA: rep = NH/NKV = 2

    // ---- load Q tile (64 x 256) ----
    const float* Qbase = Q + (size_t)q0 * QN + h * DH;
#pragma unroll
    for (int it = 0; it < 16; it++) {
        int fid = t + it * 256;
        int row = fid >> 6;
        int c4  = fid & 63;
        float4 v = *(const float4*)(Qbase + (size_t)row * QN + c4 * 4);
        float* dst = Qs + row * 257 + c4 * 4;
        dst[0] = v.x; dst[1] = v.y; dst[2] = v.z; dst[3] = v.w;
    }
    if (t < 64) { mrow[t] = -1e30f; lrow[t] = 0.f; }

    float o[4][16];
#pragma unroll
    for (int r = 0; r < 4; r++)
#pragma unroll
        for (int j = 0; j < 16; j++) o[r][j] = 0.f;

    int col[4];
#pragma unroll
    for (int c = 0; c < 4; c++) col[c] = 2 * tx + (c & 1) + (c >> 1) * 32;

    const int kb_lo = max(0, q0 - (WIN - 1)) >> 6;
    const int kb_hi = (q0 + 63) >> 6;

    for (int kb = kb_lo; kb <= kb_hi; kb++) {
        const int k0 = kb * 64;
        __syncthreads();   // protect Ks/Vs/Ss from previous iteration

        // ---- load K & V tiles (64 x 256 each) ----
        const float* Kb = K + (size_t)k0 * KVN + kvh * DH;
        const float* Vb = V + (size_t)k0 * KVN + kvh * DH;
#pragma unroll
        for (int it = 0; it < 16; it++) {
            int fid = t + it * 256;
            int row = fid >> 6;
            int c4  = fid & 63;
            float4 kv = *(const float4*)(Kb + (size_t)row * KVN + c4 * 4);
            float* kd = Ks + row * 257 + c4 * 4;
            kd[0] = kv.x; kd[1] = kv.y; kd[2] = kv.z; kd[3] = kv.w;
            float4 vv = *(const float4*)(Vb + (size_t)row * KVN + c4 * 4);
            *(float4*)(Vs + row * 260 + c4 * 4) = vv;
        }
        __syncthreads();

        // ---- scores: 4 rows x 4 keys per thread ----
        float sacc[4][4];
#pragma unroll
        for (int r = 0; r < 4; r++)
#pragma unroll
            for (int c = 0; c < 4; c++) sacc[r][c] = 0.f;

#pragma unroll 4
        for (int d = 0; d < 256; d++) {
            float qv[4], kvv[4];
#pragma unroll
            for (int r = 0; r < 4; r++) qv[r] = Qs[(4 * ty + r) * 257 + d];
#pragma unroll
            for (int c = 0; c < 4; c++) kvv[c] = Ks[col[c] * 257 + d];
#pragma unroll
            for (int r = 0; r < 4; r++)
#pragma unroll
                for (int c = 0; c < 4; c++)
                    sacc[r][c] = fmaf(qv[r], kvv[c], sacc[r][c]);
        }

        // masked logits -> Ss
#pragma unroll
        for (int r = 0; r < 4; r++) {
            int qg = q0 + 4 * ty + r;
#pragma unroll
            for (int c = 0; c < 4; c++) {
                int kg = k0 + col[c];
                bool valid = (kg <= qg) && (qg - kg < WIN);
                Ss[(4 * ty + r) * 65 + col[c]] = valid ? sacc[r][c] : -1e30f;
            }
        }
        __syncthreads();

        // ---- online softmax update (4 threads per row) ----
        {
            int row = t >> 2, seg = t & 3;
            float mx = -1e30f;
#pragma unroll
            for (int j = 0; j < 16; j++)
                mx = fmaxf(mx, Ss[row * 65 + seg * 16 + j]);
            mx = fmaxf(mx, __shfl_xor_sync(0xffffffffu, mx, 1));
            mx = fmaxf(mx, __shfl_xor_sync(0xffffffffu, mx, 2));
            float m_old = mrow[row];
            float m_new = fmaxf(m_old, mx);
            float sum = 0.f;
#pragma unroll
            for (int j = 0; j < 16; j++) {
                float p = __expf(Ss[row * 65 + seg * 16 + j] - m_new);
                Ss[row * 65 + seg * 16 + j] = p;
                sum += p;
            }
            sum += __shfl_xor_sync(0xffffffffu, sum, 1);
            sum += __shfl_xor_sync(0xffffffffu, sum, 2);
            if (seg == 0) {
                float corr = __expf(m_old - m_new);  // wipes garbage from fully-masked blocks
                mrow[row] = m_new;
                lrow[row] = lrow[row] * corr + sum;
                crow[row] = corr;
            }
        }
        __syncthreads();

        // ---- rescale accumulators + P @ V ----
        float cr[4];
#pragma unroll
        for (int r = 0; r < 4; r++) cr[r] = crow[4 * ty + r];
#pragma unroll
        for (int r = 0; r < 4; r++)
#pragma unroll
            for (int j = 0; j < 16; j++) o[r][j] *= cr[r];

#pragma unroll 2
        for (int c = 0; c < 64; c++) {
            float p[4];
#pragma unroll
            for (int r = 0; r < 4; r++) p[r] = Ss[(4 * ty + r) * 65 + c];
#pragma unroll
            for (int g = 0; g < 4; g++) {
                float4 vv = *(const float4*)(Vs + c * 260 + g * 64 + tx * 4);
#pragma unroll
                for (int r = 0; r < 4; r++) {
                    o[r][g * 4 + 0] = fmaf(p[r], vv.x, o[r][g * 4 + 0]);
                    o[r][g * 4 + 1] = fmaf(p[r], vv.y, o[r][g * 4 + 1]);
                    o[r][g * 4 + 2] = fmaf(p[r], vv.z, o[r][g * 4 + 2]);
                    o[r][g * 4 + 3] = fmaf(p[r], vv.w, o[r][g * 4 + 3]);
                }
            }
        }
    }

    // ---- finalize: divide by l, write attn output [S][NH*DH] ----
#pragma unroll
    for (int r = 0; r < 4; r++) {
        float inv = 1.f / lrow[4 * ty + r];
        float* dst = O + (size_t)(q0 + 4 * ty + r) * QN + h * DH;
#pragma unroll
        for (int g = 0; g < 4; g++) {
            float4 vv = make_float4(o[r][g * 4 + 0] * inv, o[r][g * 4 + 1] * inv,
                                    o[r][g * 4 + 2] * inv, o[r][g * 4 + 3] * inv);
            *(float4*)(dst + g * 64 + tx * 4) = vv;
        }
    }
}

// =====================================================================
// kernel_launch
// =====================================================================
extern "C" void kernel_launch(void* const* d_in, const int* in_sizes, int n_in,
                              void* d_out, int out_size)
{
    const float* hs   = (const float*)d_in[0];
    const float* cosp = (const float*)d_in[1];
    const float* sinp = (const float*)d_in[2];
    const float* wq   = (const float*)d_in[3];
    const float* wk   = (const float*)d_in[4];
    const float* wv   = (const float*)d_in[5];
    const float* wo   = (const float*)d_in[6];
    const float* qw   = (const float*)d_in[7];
    const float* kw   = (const float*)d_in[8];
    float* out = (float*)d_out;

    float *gq, *gk, *gv, *ga;
    cudaGetSymbolAddress((void**)&gq, g_q);
    cudaGetSymbolAddress((void**)&gk, g_k);
    cudaGetSymbolAddress((void**)&gv, g_v);
    cudaGetSymbolAddress((void**)&ga, g_attn);

    // QKV projections
    sgemm_kernel<<<dim3(QN / 128,  S / 128), 256>>>(hs, wq, gq, S, QN,  HID);
    sgemm_kernel<<<dim3(KVN / 128, S / 128), 256>>>(hs, wk, gk, S, KVN, HID);
    sgemm_kernel<<<dim3(KVN / 128, S / 128), 256>>>(hs, wv, gv, S, KVN, HID);

    // RMSNorm + RoPE (q, k) and RMSNorm (v)
    norm_rope_kernel<<<dim3(S, 16), 256>>>(gq, gk, gv, cosp, sinp, qw, kw);

    // Attention
    cudaFuncSetAttribute(attn_kernel, cudaFuncAttributeMaxDynamicSharedMemorySize,
                         ATT_SMEM_BYTES);
    attn_kernel<<<dim3(S / 64, NH), 256, ATT_SMEM_BYTES>>>(gq, gk, gv, ga);

    // Output projection
    sgemm_kernel<<<dim3(HID / 128, S / 128), 256>>>(ga, wo, out, S, HID, QN);
}

// round 3
// speedup vs baseline: 1.7995x; 1.7995x over previous
#include <cuda_runtime.h>
#include <cuda_bf16.h>
#include <math.h>
#include <stdint.h>

// ---------------- problem constants ----------------
#define S     2048
#define HID   2560
#define NH    8
#define NKV   4
#define DH    256
#define WIN   1024
#define QN    (NH*DH)    // 2048
#define KVN   (NKV*DH)   // 1024

// ---------------- scratch (static device memory) ----------------
__device__ float g_q[S * QN];
__device__ float g_k[S * KVN];
__device__ float g_v[S * KVN];
__device__ float g_attn[S * QN];

// hi/lo bf16 splits
__device__ __nv_bfloat16 g_hs_h[S * HID],  g_hs_l[S * HID];
__device__ __nv_bfloat16 g_wq_h[HID * QN], g_wq_l[HID * QN];
__device__ __nv_bfloat16 g_wk_h[HID * KVN], g_wk_l[HID * KVN];
__device__ __nv_bfloat16 g_wv_h[HID * KVN], g_wv_l[HID * KVN];
__device__ __nv_bfloat16 g_wo_h[QN * HID], g_wo_l[QN * HID];
__device__ __nv_bfloat16 g_at_h[S * QN],   g_at_l[S * QN];

// ---------------- PTX helpers ----------------
#define CP16(dst_u32, src_ptr) \
    asm volatile("cp.async.cg.shared.global [%0], [%1], 16;\n" :: "r"(dst_u32), "l"(src_ptr))
#define CP_COMMIT()  asm volatile("cp.async.commit_group;\n")
#define CP_WAIT0()   asm volatile("cp.async.wait_group 0;\n")

#define LDSM4(R, addr) \
    asm volatile("ldmatrix.sync.aligned.m8n8.x4.shared.b16 {%0,%1,%2,%3}, [%4];\n" \
        : "=r"((R)[0]), "=r"((R)[1]), "=r"((R)[2]), "=r"((R)[3]) : "r"(addr))
#define LDSM4T(R, addr) \
    asm volatile("ldmatrix.sync.aligned.m8n8.x4.trans.shared.b16 {%0,%1,%2,%3}, [%4];\n" \
        : "=r"((R)[0]), "=r"((R)[1]), "=r"((R)[2]), "=r"((R)[3]) : "r"(addr))

#define MMA_BF16(d, a, b0, b1) \
    asm volatile("mma.sync.aligned.m16n8k16.row.col.f32.bf16.bf16.f32 " \
        "{%0,%1,%2,%3},{%4,%5,%6,%7},{%8,%9},{%0,%1,%2,%3};\n" \
        : "+f"((d)[0]), "+f"((d)[1]), "+f"((d)[2]), "+f"((d)[3]) \
        : "r"((a)[0]), "r"((a)[1]), "r"((a)[2]), "r"((a)[3]), "r"(b0), "r"(b1))

__device__ __forceinline__ uint32_t smem_u32(const void* p) {
    return (uint32_t)__cvta_generic_to_shared(p);
}

// =====================================================================
// split fp32 -> (hi, lo) bf16
// =====================================================================
__global__ __launch_bounds__(256) void split_kernel(
    const float* __restrict__ x, __nv_bfloat16* __restrict__ h,
    __nv_bfloat16* __restrict__ l, int n)
{
    int i = (blockIdx.x * 256 + threadIdx.x) * 4;
    if (i >= n) return;
    float4 v = *(const float4*)(x + i);
    __nv_bfloat16 h0 = __float2bfloat16(v.x);
    __nv_bfloat16 h1 = __float2bfloat16(v.y);
    __nv_bfloat16 h2 = __float2bfloat16(v.z);
    __nv_bfloat16 h3 = __float2bfloat16(v.w);
    __nv_bfloat16 l0 = __float2bfloat16(v.x - __bfloat162float(h0));
    __nv_bfloat16 l1 = __float2bfloat16(v.y - __bfloat162float(h1));
    __nv_bfloat16 l2 = __float2bfloat16(v.z - __bfloat162float(h2));
    __nv_bfloat16 l3 = __float2bfloat16(v.w - __bfloat162float(h3));
    *(__nv_bfloat162*)(h + i)     = __halves2bfloat162(h0, h1);
    *(__nv_bfloat162*)(h + i + 2) = __halves2bfloat162(h2, h3);
    *(__nv_bfloat162*)(l + i)     = __halves2bfloat162(l0, l1);
    *(__nv_bfloat162*)(l + i + 2) = __halves2bfloat162(l2, l3);
}

// =====================================================================
// bf16x3 tensor-core GEMM: C = Ah*Bh + Ah*Bl + Al*Bh  (fp32 accum)
// 128x128x32 CTA tile, 8 warps (2x4), warp tile 64x32, cp.async 2-stage.
// =====================================================================
#define AS_STR 40                      // bf16 stride for A tile rows (pad 8)
#define BS_STR 136                     // bf16 stride for B tile rows (pad 8)
#define ABUF   (128 * AS_STR)          // 5120 bf16
#define BBUF   (32 * BS_STR)           // 4352 bf16
#define BUFELEM (2 * ABUF + 2 * BBUF)  // 18944 bf16
#define GEMM_SMEM_BYTES (2 * BUFELEM * 2)  // 75776 B

__global__ __launch_bounds__(256) void gemm3_kernel(
    const __nv_bfloat16* __restrict__ Ah, const __nv_bfloat16* __restrict__ Al,
    const __nv_bfloat16* __restrict__ Bh, const __nv_bfloat16* __restrict__ Bl,
    float* __restrict__ C, int M, int N, int K)
{
    extern __shared__ __nv_bfloat16 smbuf[];
    const int t    = threadIdx.x;
    const int lane = t & 31;
    const int wid  = t >> 5;
    const int wm   = wid >> 2;         // 0..1  (64-row slab)
    const int wn   = wid & 3;          // 0..3  (32-col slab)
    const int m0   = blockIdx.y * 128;
    const int n0   = blockIdx.x * 128;

    float acc[4][4][4];
#pragma unroll
    for (int mi = 0; mi < 4; mi++)
#pragma unroll
        for (int ni = 0; ni < 4; ni++)
#pragma unroll
            for (int r = 0; r < 4; r++) acc[mi][ni][r] = 0.f;

    // per-buffer smem bases (u32 shared addresses)
    uint32_t sbase[2][4];
#pragma unroll
    for (int b = 0; b < 2; b++) {
        __nv_bfloat16* p = smbuf + b * BUFELEM;
        sbase[b][0] = smem_u32(p);                    // Ah
        sbase[b][1] = smem_u32(p + ABUF);             // Al
        sbase[b][2] = smem_u32(p + 2 * ABUF);         // Bh
        sbase[b][3] = smem_u32(p + 2 * ABUF + BBUF);  // Bl
    }

    auto issue = [&](int k0, int buf) {
#pragma unroll
        for (int p = 0; p < 2; p++) {
            int id = t + p * 256;
            int am = id >> 2, ac = (id & 3) * 8;
            size_t aoff = (size_t)(m0 + am) * K + k0 + ac;
            uint32_t ad = (uint32_t)(am * AS_STR + ac) * 2;
            CP16(sbase[buf][0] + ad, Ah + aoff);
            CP16(sbase[buf][1] + ad, Al + aoff);
            int bk = id >> 4, bc = (id & 15) * 8;
            size_t boff = (size_t)(k0 + bk) * N + n0 + bc;
            uint32_t bd = (uint32_t)(bk * BS_STR + bc) * 2;
            CP16(sbase[buf][2] + bd, Bh + boff);
            CP16(sbase[buf][3] + bd, Bl + boff);
        }
        CP_COMMIT();
    };

    issue(0, 0);
    const int nIter = K / 32;

    for (int it = 0; it < nIter; it++) {
        CP_WAIT0();
        __syncthreads();
        if (it + 1 < nIter) issue((it + 1) * 32, (it + 1) & 1);

        const int buf = it & 1;
        const uint32_t ah_s = sbase[buf][0];
        const uint32_t al_s = sbase[buf][1];
        const uint32_t bh_s = sbase[buf][2];
        const uint32_t bl_s = sbase[buf][3];

#pragma unroll
        for (int ks = 0; ks < 32; ks += 16) {
            uint32_t fah[4][4], fal[4][4], fbh[2][4], fbl[2][4];

            // A fragments: ldmatrix x4 (rows 0-15 / +8 k-half by lane)
            int arow = lane & 15;
            int acol = ks + ((lane >> 4) & 1) * 8;
#pragma unroll
            for (int mi = 0; mi < 4; mi++) {
                uint32_t off = (uint32_t)((wm * 64 + mi * 16 + arow) * AS_STR + acol) * 2;
                LDSM4(fah[mi], ah_s + off);
                LDSM4(fal[mi], al_s + off);
            }

            // B fragments: ldmatrix x4.trans — covers two n8 tiles each
            int bkrow = ks + (lane & 7) + ((lane >> 3) & 1) * 8;
#pragma unroll
            for (int np = 0; np < 2; np++) {
                int bcol = wn * 32 + np * 16 + ((lane >> 4) & 1) * 8;
                uint32_t off = (uint32_t)(bkrow * BS_STR + bcol) * 2;
                LDSM4T(fbh[np], bh_s + off);
                LDSM4T(fbl[np], bl_s + off);
            }

#pragma unroll
            for (int mi = 0; mi < 4; mi++)
#pragma unroll
                for (int ni = 0; ni < 4; ni++) {
                    const uint32_t* bh2 = &fbh[ni >> 1][(ni & 1) * 2];
                    const uint32_t* bl2 = &fbl[ni >> 1][(ni & 1) * 2];
                    MMA_BF16(acc[mi][ni], fah[mi], bh2[0], bh2[1]);
                    MMA_BF16(acc[mi][ni], fah[mi], bl2[0], bl2[1]);
                    MMA_BF16(acc[mi][ni], fal[mi], bh2[0], bh2[1]);
                }
        }
        __syncthreads();
    }

    // epilogue
    int g  = lane >> 2;
    int c2 = (lane & 3) * 2;
#pragma unroll
    for (int mi = 0; mi < 4; mi++)
#pragma unroll
        for (int ni = 0; ni < 4; ni++) {
            int row = m0 + wm * 64 + mi * 16 + g;
            int col = n0 + wn * 32 + ni * 8 + c2;
            float2 v0 = make_float2(acc[mi][ni][0], acc[mi][ni][1]);
            float2 v1 = make_float2(acc[mi][ni][2], acc[mi][ni][3]);
            *(float2*)(C + (size_t)row * N + col)       = v0;
            *(float2*)(C + (size_t)(row + 8) * N + col) = v1;
        }
}

// =====================================================================
// Fused RMSNorm (+ optional weight) + RoPE, in place.
// =====================================================================
__global__ __launch_bounds__(256) void norm_rope_kernel(
    float* __restrict__ q, float* __restrict__ k, float* __restrict__ v,
    const float* __restrict__ cosp, const float* __restrict__ sinp,
    const float* __restrict__ qw, const float* __restrict__ kw)
{
    const int s   = blockIdx.x;
    const int idx = blockIdx.y;
    const int d   = threadIdx.x;

    float* base;
    const float* w;
    bool rope;
    if (idx < 8)       { base = q + (size_t)s * QN  + idx * DH;        w = qw;      rope = true;  }
    else if (idx < 12) { base = k + (size_t)s * KVN + (idx - 8) * DH;  w = kw;      rope = true;  }
    else               { base = v + (size_t)s * KVN + (idx - 12) * DH; w = nullptr; rope = false; }

    float x = base[d];
    float ss = x * x;
#pragma unroll
    for (int o = 16; o; o >>= 1) ss += __shfl_xor_sync(0xffffffffu, ss, o);

    __shared__ float wsum[8];
    if ((d & 31) == 0) wsum[d >> 5] = ss;
    __syncthreads();
    float tot = 0.f;
#pragma unroll
    for (int i = 0; i < 8; i++) tot += wsum[i];

    float inv = rsqrtf(tot * (1.0f / 256.0f) + 1e-6f);
    float y = x * inv;
    if (w) y *= w[d];

    __shared__ float sh[256];
    sh[d] = y;
    __syncthreads();

    float out = y;
    if (rope) {
        float c  = cosp[(size_t)s * DH + d];
        float si = sinp[(size_t)s * DH + d];
        float rh = (d < 128) ? -sh[d + 128] : sh[d - 128];
        out = y * c + rh * si;
    }
    base[d] = out;
}

// =====================================================================
// Flash-style fp32 attention with sliding-window causal mask.
// =====================================================================
#define ATT_SMEM_FLOATS (64*257 + 64*257 + 64*260 + 64*65 + 3*64)
#define ATT_SMEM_BYTES  (ATT_SMEM_FLOATS * 4)

__global__ __launch_bounds__(256) void attn_kernel(
    const float* __restrict__ Q, const float* __restrict__ K,
    const float* __restrict__ V, float* __restrict__ O)
{
    extern __shared__ float sm[];
    float* Qs   = sm;
    float* Ks   = Qs + 64 * 257;
    float* Vs   = Ks + 64 * 257;
    float* Ss   = Vs + 64 * 260;
    float* mrow = Ss + 64 * 65;
    float* lrow = mrow + 64;
    float* crow = lrow + 64;

    const int t  = threadIdx.x;
    const int tx = t & 15;
    const int ty = t >> 4;
    const int q0 = blockIdx.x * 64;
    const int h  = blockIdx.y;
    const int kvh = h >> 1;

    const float* Qbase = Q + (size_t)q0 * QN + h * DH;
#pragma unroll
    for (int it = 0; it < 16; it++) {
        int fid = t + it * 256;
        int row = fid >> 6;
        int c4  = fid & 63;
        float4 v = *(const float4*)(Qbase + (size_t)row * QN + c4 * 4);
        float* dst = Qs + row * 257 + c4 * 4;
        dst[0] = v.x; dst[1] = v.y; dst[2] = v.z; dst[3] = v.w;
    }
    if (t < 64) { mrow[t] = -1e30f; lrow[t] = 0.f; }

    float o[4][16];
#pragma unroll
    for (int r = 0; r < 4; r++)
#pragma unroll
        for (int j = 0; j < 16; j++) o[r][j] = 0.f;

    int col[4];
#pragma unroll
    for (int c = 0; c < 4; c++) col[c] = 2 * tx + (c & 1) + (c >> 1) * 32;

    const int kb_lo = max(0, q0 - (WIN - 1)) >> 6;
    const int kb_hi = (q0 + 63) >> 6;

    for (int kb = kb_lo; kb <= kb_hi; kb++) {
        const int k0 = kb * 64;
        __syncthreads();

        const float* Kb = K + (size_t)k0 * KVN + kvh * DH;
        const float* Vb = V + (size_t)k0 * KVN + kvh * DH;
#pragma unroll
        for (int it = 0; it < 16; it++) {
            int fid = t + it * 256;
            int row = fid >> 6;
            int c4  = fid & 63;
            float4 kv = *(const float4*)(Kb + (size_t)row * KVN + c4 * 4);
            float* kd = Ks + row * 257 + c4 * 4;
            kd[0] = kv.x; kd[1] = kv.y; kd[2] = kv.z; kd[3] = kv.w;
            float4 vv = *(const float4*)(Vb + (size_t)row * KVN + c4 * 4);
            *(float4*)(Vs + row * 260 + c4 * 4) = vv;
        }
        __syncthreads();

        float sacc[4][4];
#pragma unroll
        for (int r = 0; r < 4; r++)
#pragma unroll
            for (int c = 0; c < 4; c++) sacc[r][c] = 0.f;

#pragma unroll 4
        for (int d = 0; d < 256; d++) {
            float qv[4], kvv[4];
#pragma unroll
            for (int r = 0; r < 4; r++) qv[r] = Qs[(4 * ty + r) * 257 + d];
#pragma unroll
            for (int c = 0; c < 4; c++) kvv[c] = Ks[col[c] * 257 + d];
#pragma unroll
            for (int r = 0; r < 4; r++)
#pragma unroll
                for (int c = 0; c < 4; c++)
                    sacc[r][c] = fmaf(qv[r], kvv[c], sacc[r][c]);
        }

#pragma unroll
        for (int r = 0; r < 4; r++) {
            int qg = q0 + 4 * ty + r;
#pragma unroll
            for (int c = 0; c < 4; c++) {
                int kg = k0 + col[c];
                bool valid = (kg <= qg) && (qg - kg < WIN);
                Ss[(4 * ty + r) * 65 + col[c]] = valid ? sacc[r][c] : -1e30f;
            }
        }
        __syncthreads();

        {
            int row = t >> 2, seg = t & 3;
            float mx = -1e30f;
#pragma unroll
            for (int j = 0; j < 16; j++)
                mx = fmaxf(mx, Ss[row * 65 + seg * 16 + j]);
            mx = fmaxf(mx, __shfl_xor_sync(0xffffffffu, mx, 1));
            mx = fmaxf(mx, __shfl_xor_sync(0xffffffffu, mx, 2));
            float m_old = mrow[row];
            float m_new = fmaxf(m_old, mx);
            float sum = 0.f;
#pragma unroll
            for (int j = 0; j < 16; j++) {
                float p = __expf(Ss[row * 65 + seg * 16 + j] - m_new);
                Ss[row * 65 + seg * 16 + j] = p;
                sum += p;
            }
            sum += __shfl_xor_sync(0xffffffffu, sum, 1);
            sum += __shfl_xor_sync(0xffffffffu, sum, 2);
            if (seg == 0) {
                float corr = __expf(m_old - m_new);
                mrow[row] = m_new;
                lrow[row] = lrow[row] * corr + sum;
                crow[row] = corr;
            }
        }
        __syncthreads();

        float cr[4];
#pragma unroll
        for (int r = 0; r < 4; r++) cr[r] = crow[4 * ty + r];
#pragma unroll
        for (int r = 0; r < 4; r++)
#pragma unroll
            for (int j = 0; j < 16; j++) o[r][j] *= cr[r];

#pragma unroll 2
        for (int c = 0; c < 64; c++) {
            float p[4];
#pragma unroll
            for (int r = 0; r < 4; r++) p[r] = Ss[(4 * ty + r) * 65 + c];
#pragma unroll
            for (int g = 0; g < 4; g++) {
                float4 vv = *(const float4*)(Vs + c * 260 + g * 64 + tx * 4);
#pragma unroll
                for (int r = 0; r < 4; r++) {
                    o[r][g * 4 + 0] = fmaf(p[r], vv.x, o[r][g * 4 + 0]);
                    o[r][g * 4 + 1] = fmaf(p[r], vv.y, o[r][g * 4 + 1]);
                    o[r][g * 4 + 2] = fmaf(p[r], vv.z, o[r][g * 4 + 2]);
                    o[r][g * 4 + 3] = fmaf(p[r], vv.w, o[r][g * 4 + 3]);
                }
            }
        }
    }

#pragma unroll
    for (int r = 0; r < 4; r++) {
        float inv = 1.f / lrow[4 * ty + r];
        float* dst = O + (size_t)(q0 + 4 * ty + r) * QN + h * DH;
#pragma unroll
        for (int g = 0; g < 4; g++) {
            float4 vv = make_float4(o[r][g * 4 + 0] * inv, o[r][g * 4 + 1] * inv,
                                    o[r][g * 4 + 2] * inv, o[r][g * 4 + 3] * inv);
            *(float4*)(dst + g * 64 + tx * 4) = vv;
        }
    }
}

// =====================================================================
// kernel_launch
// =====================================================================
extern "C" void kernel_launch(void* const* d_in, const int* in_sizes, int n_in,
                              void* d_out, int out_size)
{
    const float* hs   = (const float*)d_in[0];
    const float* cosp = (const float*)d_in[1];
    const float* sinp = (const float*)d_in[2];
    const float* wq   = (const float*)d_in[3];
    const float* wk   = (const float*)d_in[4];
    const float* wv   = (const float*)d_in[5];
    const float* wo   = (const float*)d_in[6];
    const float* qw   = (const float*)d_in[7];
    const float* kw   = (const float*)d_in[8];
    float* out = (float*)d_out;

    float *gq, *gk, *gv, *ga;
    cudaGetSymbolAddress((void**)&gq, g_q);
    cudaGetSymbolAddress((void**)&gk, g_k);
    cudaGetSymbolAddress((void**)&gv, g_v);
    cudaGetSymbolAddress((void**)&ga, g_attn);

    __nv_bfloat16 *hsh, *hsl, *wqh, *wql, *wkh, *wkl, *wvh, *wvl, *woh, *wol, *ath, *atl;
    cudaGetSymbolAddress((void**)&hsh, g_hs_h); cudaGetSymbolAddress((void**)&hsl, g_hs_l);
    cudaGetSymbolAddress((void**)&wqh, g_wq_h); cudaGetSymbolAddress((void**)&wql, g_wq_l);
    cudaGetSymbolAddress((void**)&wkh, g_wk_h); cudaGetSymbolAddress((void**)&wkl, g_wk_l);
    cudaGetSymbolAddress((void**)&wvh, g_wv_h); cudaGetSymbolAddress((void**)&wvl, g_wv_l);
    cudaGetSymbolAddress((void**)&woh, g_wo_h); cudaGetSymbolAddress((void**)&wol, g_wo_l);
    cudaGetSymbolAddress((void**)&ath, g_at_h); cudaGetSymbolAddress((void**)&atl, g_at_l);

    cudaFuncSetAttribute(gemm3_kernel, cudaFuncAttributeMaxDynamicSharedMemorySize,
                         GEMM_SMEM_BYTES);
    cudaFuncSetAttribute(attn_kernel, cudaFuncAttributeMaxDynamicSharedMemorySize,
                         ATT_SMEM_BYTES);

    // hi/lo splits of activations + weights
    split_kernel<<<(S * HID / 4 + 255) / 256, 256>>>(hs, hsh, hsl, S * HID);
    split_kernel<<<(HID * QN / 4 + 255) / 256, 256>>>(wq, wqh, wql, HID * QN);
    split_kernel<<<(HID * KVN / 4 + 255) / 256, 256>>>(wk, wkh, wkl, HID * KVN);
    split_kernel<<<(HID * KVN / 4 + 255) / 256, 256>>>(wv, wvh, wvl, HID * KVN);
    split_kernel<<<(QN * HID / 4 + 255) / 256, 256>>>(wo, woh, wol, QN * HID);

    // QKV projections on tensor cores
    gemm3_kernel<<<dim3(QN / 128,  S / 128), 256, GEMM_SMEM_BYTES>>>(
        hsh, hsl, wqh, wql, gq, S, QN, HID);
    gemm3_kernel<<<dim3(KVN / 128, S / 128), 256, GEMM_SMEM_BYTES>>>(
        hsh, hsl, wkh, wkl, gk, S, KVN, HID);
    gemm3_kernel<<<dim3(KVN / 128, S / 128), 256, GEMM_SMEM_BYTES>>>(
        hsh, hsl, wvh, wvl, gv, S, KVN, HID);

    // RMSNorm + RoPE
    norm_rope_kernel<<<dim3(S, 16), 256>>>(gq, gk, gv, cosp, sinp, qw, kw);

    // Attention (fp32)
    attn_kernel<<<dim3(S / 64, NH), 256, ATT_SMEM_BYTES>>>(gq, gk, gv, ga);

    // Output projection
    split_kernel<<<(S * QN / 4 + 255) / 256, 256>>>(ga, ath, atl, S * QN);
    gemm3_kernel<<<dim3(HID / 128, S / 128), 256, GEMM_SMEM_BYTES>>>(
        ath, atl, woh, wol, out, S, HID, QN);
}

// round 4
// speedup vs baseline: 2.6553x; 1.4756x over previous
#include <cuda_runtime.h>
#include <cuda_bf16.h>
#include <math.h>
#include <stdint.h>

// ---------------- problem constants ----------------
#define S     2048
#define HID   2560
#define NH    8
#define NKV   4
#define DH    256
#define WIN   1024
#define QN    (NH*DH)    // 2048
#define KVN   (NKV*DH)   // 1024

// ---------------- scratch (static device memory) ----------------
__device__ float g_q[S * QN];
__device__ float g_k[S * KVN];
__device__ float g_v[S * KVN];
__device__ float g_attn[S * QN];

// hi/lo bf16 splits
__device__ __nv_bfloat16 g_hs_h[S * HID],  g_hs_l[S * HID];
__device__ __nv_bfloat16 g_wq_h[HID * QN], g_wq_l[HID * QN];
__device__ __nv_bfloat16 g_wk_h[HID * KVN], g_wk_l[HID * KVN];
__device__ __nv_bfloat16 g_wv_h[HID * KVN], g_wv_l[HID * KVN];
__device__ __nv_bfloat16 g_wo_h[QN * HID], g_wo_l[QN * HID];
__device__ __nv_bfloat16 g_at_h[S * QN],   g_at_l[S * QN];

// attention operand splits (post norm+rope)
__device__ __nv_bfloat16 g_qh[S * QN],  g_ql[S * QN];
__device__ __nv_bfloat16 g_kh[S * KVN], g_kl[S * KVN];
__device__ __nv_bfloat16 g_vh[S * KVN], g_vl[S * KVN];

// ---------------- PTX helpers ----------------
#define CP16(dst_u32, src_ptr) \
    asm volatile("cp.async.cg.shared.global [%0], [%1], 16;\n" :: "r"(dst_u32), "l"(src_ptr))
#define CP_COMMIT()  asm volatile("cp.async.commit_group;\n")
#define CP_WAIT0()   asm volatile("cp.async.wait_group 0;\n")

#define LDSM4(R, addr) \
    asm volatile("ldmatrix.sync.aligned.m8n8.x4.shared.b16 {%0,%1,%2,%3}, [%4];\n" \
        : "=r"((R)[0]), "=r"((R)[1]), "=r"((R)[2]), "=r"((R)[3]) : "r"(addr))
#define LDSM4T(R, addr) \
    asm volatile("ldmatrix.sync.aligned.m8n8.x4.trans.shared.b16 {%0,%1,%2,%3}, [%4];\n" \
        : "=r"((R)[0]), "=r"((R)[1]), "=r"((R)[2]), "=r"((R)[3]) : "r"(addr))

#define MMA_BF16(d, a, b0, b1) \
    asm volatile("mma.sync.aligned.m16n8k16.row.col.f32.bf16.bf16.f32 " \
        "{%0,%1,%2,%3},{%4,%5,%6,%7},{%8,%9},{%0,%1,%2,%3};\n" \
        : "+f"((d)[0]), "+f"((d)[1]), "+f"((d)[2]), "+f"((d)[3]) \
        : "r"((a)[0]), "r"((a)[1]), "r"((a)[2]), "r"((a)[3]), "r"(b0), "r"(b1))

__device__ __forceinline__ uint32_t smem_u32(const void* p) {
    return (uint32_t)__cvta_generic_to_shared(p);
}

// =====================================================================
// split fp32 -> (hi, lo) bf16
// =====================================================================
__global__ __launch_bounds__(256) void split_kernel(
    const float* __restrict__ x, __nv_bfloat16* __restrict__ h,
    __nv_bfloat16* __restrict__ l, int n)
{
    int i = (blockIdx.x * 256 + threadIdx.x) * 4;
    if (i >= n) return;
    float4 v = *(const float4*)(x + i);
    __nv_bfloat16 h0 = __float2bfloat16(v.x);
    __nv_bfloat16 h1 = __float2bfloat16(v.y);
    __nv_bfloat16 h2 = __float2bfloat16(v.z);
    __nv_bfloat16 h3 = __float2bfloat16(v.w);
    __nv_bfloat16 l0 = __float2bfloat16(v.x - __bfloat162float(h0));
    __nv_bfloat16 l1 = __float2bfloat16(v.y - __bfloat162float(h1));
    __nv_bfloat16 l2 = __float2bfloat16(v.z - __bfloat162float(h2));
    __nv_bfloat16 l3 = __float2bfloat16(v.w - __bfloat162float(h3));
    *(__nv_bfloat162*)(h + i)     = __halves2bfloat162(h0, h1);
    *(__nv_bfloat162*)(h + i + 2) = __halves2bfloat162(h2, h3);
    *(__nv_bfloat162*)(l + i)     = __halves2bfloat162(l0, l1);
    *(__nv_bfloat162*)(l + i + 2) = __halves2bfloat162(l2, l3);
}

// =====================================================================
// bf16x3 tensor-core GEMM (unchanged from R3)
// =====================================================================
#define AS_STR 40
#define BS_STR 136
#define ABUF   (128 * AS_STR)
#define BBUF   (32 * BS_STR)
#define BUFELEM (2 * ABUF + 2 * BBUF)
#define GEMM_SMEM_BYTES (2 * BUFELEM * 2)

__global__ __launch_bounds__(256) void gemm3_kernel(
    const __nv_bfloat16* __restrict__ Ah, const __nv_bfloat16* __restrict__ Al,
    const __nv_bfloat16* __restrict__ Bh, const __nv_bfloat16* __restrict__ Bl,
    float* __restrict__ C, int M, int N, int K)
{
    extern __shared__ __nv_bfloat16 smbuf[];
    const int t    = threadIdx.x;
    const int lane = t & 31;
    const int wid  = t >> 5;
    const int wm   = wid >> 2;
    const int wn   = wid & 3;
    const int m0   = blockIdx.y * 128;
    const int n0   = blockIdx.x * 128;

    float acc[4][4][4];
#pragma unroll
    for (int mi = 0; mi < 4; mi++)
#pragma unroll
        for (int ni = 0; ni < 4; ni++)
#pragma unroll
            for (int r = 0; r < 4; r++) acc[mi][ni][r] = 0.f;

    uint32_t sbase[2][4];
#pragma unroll
    for (int b = 0; b < 2; b++) {
        __nv_bfloat16* p = smbuf + b * BUFELEM;
        sbase[b][0] = smem_u32(p);
        sbase[b][1] = smem_u32(p + ABUF);
        sbase[b][2] = smem_u32(p + 2 * ABUF);
        sbase[b][3] = smem_u32(p + 2 * ABUF + BBUF);
    }

    auto issue = [&](int k0, int buf) {
#pragma unroll
        for (int p = 0; p < 2; p++) {
            int id = t + p * 256;
            int am = id >> 2, ac = (id & 3) * 8;
            size_t aoff = (size_t)(m0 + am) * K + k0 + ac;
            uint32_t ad = (uint32_t)(am * AS_STR + ac) * 2;
            CP16(sbase[buf][0] + ad, Ah + aoff);
            CP16(sbase[buf][1] + ad, Al + aoff);
            int bk = id >> 4, bc = (id & 15) * 8;
            size_t boff = (size_t)(k0 + bk) * N + n0 + bc;
            uint32_t bd = (uint32_t)(bk * BS_STR + bc) * 2;
            CP16(sbase[buf][2] + bd, Bh + boff);
            CP16(sbase[buf][3] + bd, Bl + boff);
        }
        CP_COMMIT();
    };

    issue(0, 0);
    const int nIter = K / 32;

    for (int it = 0; it < nIter; it++) {
        CP_WAIT0();
        __syncthreads();
        if (it + 1 < nIter) issue((it + 1) * 32, (it + 1) & 1);

        const int buf = it & 1;
        const uint32_t ah_s = sbase[buf][0];
        const uint32_t al_s = sbase[buf][1];
        const uint32_t bh_s = sbase[buf][2];
        const uint32_t bl_s = sbase[buf][3];

#pragma unroll
        for (int ks = 0; ks < 32; ks += 16) {
            uint32_t fah[4][4], fal[4][4], fbh[2][4], fbl[2][4];

            int arow = lane & 15;
            int acol = ks + ((lane >> 4) & 1) * 8;
#pragma unroll
            for (int mi = 0; mi < 4; mi++) {
                uint32_t off = (uint32_t)((wm * 64 + mi * 16 + arow) * AS_STR + acol) * 2;
                LDSM4(fah[mi], ah_s + off);
                LDSM4(fal[mi], al_s + off);
            }

            int bkrow = ks + (lane & 7) + ((lane >> 3) & 1) * 8;
#pragma unroll
            for (int np = 0; np < 2; np++) {
                int bcol = wn * 32 + np * 16 + ((lane >> 4) & 1) * 8;
                uint32_t off = (uint32_t)(bkrow * BS_STR + bcol) * 2;
                LDSM4T(fbh[np], bh_s + off);
                LDSM4T(fbl[np], bl_s + off);
            }

#pragma unroll
            for (int mi = 0; mi < 4; mi++)
#pragma unroll
                for (int ni = 0; ni < 4; ni++) {
                    const uint32_t* bh2 = &fbh[ni >> 1][(ni & 1) * 2];
                    const uint32_t* bl2 = &fbl[ni >> 1][(ni & 1) * 2];
                    MMA_BF16(acc[mi][ni], fah[mi], bh2[0], bh2[1]);
                    MMA_BF16(acc[mi][ni], fah[mi], bl2[0], bl2[1]);
                    MMA_BF16(acc[mi][ni], fal[mi], bh2[0], bh2[1]);
                }
        }
        __syncthreads();
    }

    int g  = lane >> 2;
    int c2 = (lane & 3) * 2;
#pragma unroll
    for (int mi = 0; mi < 4; mi++)
#pragma unroll
        for (int ni = 0; ni < 4; ni++) {
            int row = m0 + wm * 64 + mi * 16 + g;
            int col = n0 + wn * 32 + ni * 8 + c2;
            float2 v0 = make_float2(acc[mi][ni][0], acc[mi][ni][1]);
            float2 v1 = make_float2(acc[mi][ni][2], acc[mi][ni][3]);
            *(float2*)(C + (size_t)row * N + col)       = v0;
            *(float2*)(C + (size_t)(row + 8) * N + col) = v1;
        }
}

// =====================================================================
// Fused RMSNorm (+weight) + RoPE, emitting bf16 hi/lo operands.
// =====================================================================
__global__ __launch_bounds__(256) void norm_rope_kernel(
    const float* __restrict__ q, const float* __restrict__ k, const float* __restrict__ v,
    const float* __restrict__ cosp, const float* __restrict__ sinp,
    const float* __restrict__ qw, const float* __restrict__ kw,
    __nv_bfloat16* __restrict__ qh, __nv_bfloat16* __restrict__ ql,
    __nv_bfloat16* __restrict__ kh, __nv_bfloat16* __restrict__ kl,
    __nv_bfloat16* __restrict__ vh, __nv_bfloat16* __restrict__ vl)
{
    const int s   = blockIdx.x;
    const int idx = blockIdx.y;
    const int d   = threadIdx.x;

    const float* base;
    const float* w;
    __nv_bfloat16 *oh, *ol;
    bool rope;
    if (idx < 8) {
        base = q + (size_t)s * QN + idx * DH; w = qw; rope = true;
        oh = qh + (size_t)s * QN + idx * DH; ol = ql + (size_t)s * QN + idx * DH;
    } else if (idx < 12) {
        base = k + (size_t)s * KVN + (idx - 8) * DH; w = kw; rope = true;
        oh = kh + (size_t)s * KVN + (idx - 8) * DH; ol = kl + (size_t)s * KVN + (idx - 8) * DH;
    } else {
        base = v + (size_t)s * KVN + (idx - 12) * DH; w = nullptr; rope = false;
        oh = vh + (size_t)s * KVN + (idx - 12) * DH; ol = vl + (size_t)s * KVN + (idx - 12) * DH;
    }

    float x = base[d];
    float ss = x * x;
#pragma unroll
    for (int o = 16; o; o >>= 1) ss += __shfl_xor_sync(0xffffffffu, ss, o);

    __shared__ float wsum[8];
    if ((d & 31) == 0) wsum[d >> 5] = ss;
    __syncthreads();
    float tot = 0.f;
#pragma unroll
    for (int i = 0; i < 8; i++) tot += wsum[i];

    float inv = rsqrtf(tot * (1.0f / 256.0f) + 1e-6f);
    float y = x * inv;
    if (w) y *= w[d];

    __shared__ float sh[256];
    sh[d] = y;
    __syncthreads();

    float out = y;
    if (rope) {
        float c  = cosp[(size_t)s * DH + d];
        float si = sinp[(size_t)s * DH + d];
        float rh = (d < 128) ? -sh[d + 128] : sh[d - 128];
        out = y * c + rh * si;
    }
    __nv_bfloat16 hb = __float2bfloat16(out);
    oh[d] = hb;
    ol[d] = __float2bfloat16(out - __bfloat162float(hb));
}

// =====================================================================
// Tensor-core flash attention (bf16x3), sliding-window causal.
// CTA: 256 thr (8 warps x 16 q-rows = 128-q tile) per head. 32-key blocks.
// =====================================================================
#define KT    32
#define ASTR  264     // padded bf16 row stride (528 B -> conflict-free ldmatrix)
#define ATT_SM_ELEM (2*128*ASTR + 4*KT*ASTR)
#define ATT_SM_BYTES (ATT_SM_ELEM * 2)

__global__ __launch_bounds__(256, 1) void attn_tc_kernel(
    const __nv_bfloat16* __restrict__ Qh, const __nv_bfloat16* __restrict__ Ql,
    const __nv_bfloat16* __restrict__ Kh, const __nv_bfloat16* __restrict__ Kl,
    const __nv_bfloat16* __restrict__ Vh, const __nv_bfloat16* __restrict__ Vl,
    float* __restrict__ Og)
{
    extern __shared__ __nv_bfloat16 sm2[];
    const int t    = threadIdx.x;
    const int lane = t & 31;
    const int w    = t >> 5;            // warp 0..7 -> q rows [16w, 16w+15]
    const int q0   = blockIdx.x * 128;
    const int h    = blockIdx.y;
    const int kvh  = h >> 1;

    const uint32_t sQh = smem_u32(sm2);
    const uint32_t sQl = sQh + 128 * ASTR * 2;
    const uint32_t sKh = sQl + 128 * ASTR * 2;
    const uint32_t sKl = sKh + KT * ASTR * 2;
    const uint32_t sVh = sKl + KT * ASTR * 2;
    const uint32_t sVl = sVh + KT * ASTR * 2;

    // ---- load Q tile (hi/lo) ----
    const __nv_bfloat16* gqh = Qh + (size_t)q0 * QN + h * DH;
    const __nv_bfloat16* gql = Ql + (size_t)q0 * QN + h * DH;
#pragma unroll
    for (int it = 0; it < 16; it++) {
        int id = t + it * 256;
        int row = id >> 5, ch = id & 31;
        uint32_t d = (uint32_t)(row * ASTR + ch * 8) * 2;
        size_t g = (size_t)row * QN + ch * 8;
        CP16(sQh + d, gqh + g);
        CP16(sQl + d, gql + g);
    }
    CP_COMMIT();

    float o[32][4];
#pragma unroll
    for (int dt = 0; dt < 32; dt++)
#pragma unroll
        for (int r = 0; r < 4; r++) o[dt][r] = 0.f;
    float mrow[2] = {-1e30f, -1e30f};
    float lrow[2] = {0.f, 0.f};

    CP_WAIT0();
    __syncthreads();

    const int kb_lo = max(0, q0 - (WIN - 1)) >> 5;
    const int kb_hi = (q0 + 127) >> 5;
    const int qw_lo = q0 + w * 16;
    const int gq_row = lane >> 2;       // g
    const int t4 = lane & 3;

    for (int kb = kb_lo; kb <= kb_hi; kb++) {
        const int k0 = kb * KT;
        __syncthreads();     // previous iteration's consumers done

        // ---- load K/V hi/lo (32 x 256 each) ----
        {
            const __nv_bfloat16* gkh = Kh + (size_t)k0 * KVN + kvh * DH;
            const __nv_bfloat16* gkl = Kl + (size_t)k0 * KVN + kvh * DH;
            const __nv_bfloat16* gvh = Vh + (size_t)k0 * KVN + kvh * DH;
            const __nv_bfloat16* gvl = Vl + (size_t)k0 * KVN + kvh * DH;
#pragma unroll
            for (int it = 0; it < 4; it++) {
                int id = t + it * 256;
                int row = id >> 5, ch = id & 31;
                uint32_t d = (uint32_t)(row * ASTR + ch * 8) * 2;
                size_t g = (size_t)row * KVN + ch * 8;
                CP16(sKh + d, gkh + g);
                CP16(sKl + d, gkl + g);
                CP16(sVh + d, gvh + g);
                CP16(sVl + d, gvl + g);
            }
        }
        CP_COMMIT();
        CP_WAIT0();
        __syncthreads();

        // warp-level window check
        bool active = (k0 <= qw_lo + 15) && (k0 + KT - 1 >= qw_lo - (WIN - 1));
        if (!active) continue;

        // ---- scores: S[16 x 32] fp32, bf16x3 ----
        float s[4][4];
#pragma unroll
        for (int tl = 0; tl < 4; tl++)
#pragma unroll
            for (int r = 0; r < 4; r++) s[tl][r] = 0.f;

#pragma unroll
        for (int dc = 0; dc < 16; dc++) {
            uint32_t qa[4], qb[4], k1h[4], k2h[4], k1l[4], k2l[4];
            uint32_t qoff = (uint32_t)((w * 16 + (lane & 15)) * ASTR + dc * 16 + (lane >> 4) * 8) * 2;
            LDSM4(qa, sQh + qoff);
            LDSM4(qb, sQl + qoff);
            uint32_t koff = (uint32_t)((lane & 15) * ASTR + dc * 16 + (lane >> 4) * 8) * 2;
            LDSM4(k1h, sKh + koff);
            LDSM4(k2h, sKh + koff + 16 * ASTR * 2);
            LDSM4(k1l, sKl + koff);
            LDSM4(k2l, sKl + koff + 16 * ASTR * 2);

            MMA_BF16(s[0], qa, k1h[0], k1h[2]);
            MMA_BF16(s[1], qa, k1h[1], k1h[3]);
            MMA_BF16(s[2], qa, k2h[0], k2h[2]);
            MMA_BF16(s[3], qa, k2h[1], k2h[3]);
            MMA_BF16(s[0], qa, k1l[0], k1l[2]);
            MMA_BF16(s[1], qa, k1l[1], k1l[3]);
            MMA_BF16(s[2], qa, k2l[0], k2l[2]);
            MMA_BF16(s[3], qa, k2l[1], k2l[3]);
            MMA_BF16(s[0], qb, k1h[0], k1h[2]);
            MMA_BF16(s[1], qb, k1h[1], k1h[3]);
            MMA_BF16(s[2], qb, k2h[0], k2h[2]);
            MMA_BF16(s[3], qb, k2h[1], k2h[3]);
        }

        // ---- mask + online softmax (warp-local) ----
        float corr[2];
#pragma unroll
        for (int r = 0; r < 2; r++) {
            int qg = qw_lo + gq_row + r * 8;
            float mx = -1e30f;
#pragma unroll
            for (int tl = 0; tl < 4; tl++) {
#pragma unroll
                for (int c = 0; c < 2; c++) {
                    int kg = k0 + tl * 8 + 2 * t4 + c;
                    bool ok = (kg <= qg) && (qg - kg < WIN);
                    if (!ok) s[tl][r * 2 + c] = -1e30f;
                    mx = fmaxf(mx, s[tl][r * 2 + c]);
                }
            }
            mx = fmaxf(mx, __shfl_xor_sync(0xffffffffu, mx, 1));
            mx = fmaxf(mx, __shfl_xor_sync(0xffffffffu, mx, 2));
            float m_new = fmaxf(mrow[r], mx);
            float mexp = (m_new <= -1e29f) ? 0.f : m_new;
            float sum = 0.f;
#pragma unroll
            for (int tl = 0; tl < 4; tl++) {
#pragma unroll
                for (int c = 0; c < 2; c++) {
                    float p = __expf(s[tl][r * 2 + c] - mexp);
                    s[tl][r * 2 + c] = p;
                    sum += p;
                }
            }
            sum += __shfl_xor_sync(0xffffffffu, sum, 1);
            sum += __shfl_xor_sync(0xffffffffu, sum, 2);
            corr[r] = __expf(mrow[r] - m_new);
            mrow[r] = m_new;
            lrow[r] = lrow[r] * corr[r] + sum;
        }

        // ---- P -> bf16 hi/lo A-fragments ----
        uint32_t ph[2][4], pl[2][4];
#pragma unroll
        for (int kc = 0; kc < 2; kc++) {
#pragma unroll
            for (int r2 = 0; r2 < 4; r2++) {
                int tl = kc * 2 + (r2 >> 1);
                int r  = r2 & 1;
                float p0 = s[tl][r * 2 + 0];
                float p1 = s[tl][r * 2 + 1];
                __nv_bfloat16 h0 = __float2bfloat16(p0);
                __nv_bfloat16 h1 = __float2bfloat16(p1);
                __nv_bfloat16 l0 = __float2bfloat16(p0 - __bfloat162float(h0));
                __nv_bfloat16 l1 = __float2bfloat16(p1 - __bfloat162float(h1));
                __nv_bfloat162 hh = __halves2bfloat162(h0, h1);
                __nv_bfloat162 ll = __halves2bfloat162(l0, l1);
                ph[kc][r2] = *(uint32_t*)&hh;
                pl[kc][r2] = *(uint32_t*)&ll;
            }
        }

        // ---- rescale O, then P @ V (bf16x3) ----
#pragma unroll
        for (int dt = 0; dt < 32; dt++) {
            o[dt][0] *= corr[0]; o[dt][1] *= corr[0];
            o[dt][2] *= corr[1]; o[dt][3] *= corr[1];
        }

#pragma unroll
        for (int dg = 0; dg < 16; dg++) {
#pragma unroll
            for (int kc = 0; kc < 2; kc++) {
                uint32_t vh4[4], vl4[4];
                uint32_t voff = (uint32_t)((kc * 16 + (lane & 7) + ((lane >> 3) & 1) * 8) * ASTR
                                           + dg * 16 + ((lane >> 4) & 1) * 8) * 2;
                LDSM4T(vh4, sVh + voff);
                LDSM4T(vl4, sVl + voff);
                MMA_BF16(o[2 * dg],     ph[kc], vh4[0], vh4[1]);
                MMA_BF16(o[2 * dg + 1], ph[kc], vh4[2], vh4[3]);
                MMA_BF16(o[2 * dg],     pl[kc], vh4[0], vh4[1]);
                MMA_BF16(o[2 * dg + 1], pl[kc], vh4[2], vh4[3]);
                MMA_BF16(o[2 * dg],     ph[kc], vl4[0], vl4[1]);
                MMA_BF16(o[2 * dg + 1], ph[kc], vl4[2], vl4[3]);
            }
        }
    }

    // ---- finalize ----
    float inv0 = 1.f / lrow[0];
    float inv1 = 1.f / lrow[1];
    float* dst0 = Og + (size_t)(q0 + w * 16 + gq_row) * QN + h * DH;
    float* dst1 = dst0 + (size_t)8 * QN;
#pragma unroll
    for (int dt = 0; dt < 32; dt++) {
        int col = dt * 8 + 2 * t4;
        *(float2*)(dst0 + col) = make_float2(o[dt][0] * inv0, o[dt][1] * inv0);
        *(float2*)(dst1 + col) = make_float2(o[dt][2] * inv1, o[dt][3] * inv1);
    }
}

// =====================================================================
// kernel_launch
// =====================================================================
extern "C" void kernel_launch(void* const* d_in, const int* in_sizes, int n_in,
                              void* d_out, int out_size)
{
    const float* hs   = (const float*)d_in[0];
    const float* cosp = (const float*)d_in[1];
    const float* sinp = (const float*)d_in[2];
    const float* wq   = (const float*)d_in[3];
    const float* wk   = (const float*)d_in[4];
    const float* wv   = (const float*)d_in[5];
    const float* wo   = (const float*)d_in[6];
    const float* qw   = (const float*)d_in[7];
    const float* kw   = (const float*)d_in[8];
    float* out = (float*)d_out;

    float *gq, *gk, *gv, *ga;
    cudaGetSymbolAddress((void**)&gq, g_q);
    cudaGetSymbolAddress((void**)&gk, g_k);
    cudaGetSymbolAddress((void**)&gv, g_v);
    cudaGetSymbolAddress((void**)&ga, g_attn);

    __nv_bfloat16 *hsh, *hsl, *wqh, *wql, *wkh, *wkl, *wvh, *wvl, *woh, *wol, *ath, *atl;
    __nv_bfloat16 *qh, *ql, *kh, *kl, *vh, *vl;
    cudaGetSymbolAddress((void**)&hsh, g_hs_h); cudaGetSymbolAddress((void**)&hsl, g_hs_l);
    cudaGetSymbolAddress((void**)&wqh, g_wq_h); cudaGetSymbolAddress((void**)&wql, g_wq_l);
    cudaGetSymbolAddress((void**)&wkh, g_wk_h); cudaGetSymbolAddress((void**)&wkl, g_wk_l);
    cudaGetSymbolAddress((void**)&wvh, g_wv_h); cudaGetSymbolAddress((void**)&wvl, g_wv_l);
    cudaGetSymbolAddress((void**)&woh, g_wo_h); cudaGetSymbolAddress((void**)&wol, g_wo_l);
    cudaGetSymbolAddress((void**)&ath, g_at_h); cudaGetSymbolAddress((void**)&atl, g_at_l);
    cudaGetSymbolAddress((void**)&qh, g_qh);    cudaGetSymbolAddress((void**)&ql, g_ql);
    cudaGetSymbolAddress((void**)&kh, g_kh);    cudaGetSymbolAddress((void**)&kl, g_kl);
    cudaGetSymbolAddress((void**)&vh, g_vh);    cudaGetSymbolAddress((void**)&vl, g_vl);

    cudaFuncSetAttribute(gemm3_kernel, cudaFuncAttributeMaxDynamicSharedMemorySize,
                         GEMM_SMEM_BYTES);
    cudaFuncSetAttribute(attn_tc_kernel, cudaFuncAttributeMaxDynamicSharedMemorySize,
                         ATT_SM_BYTES);

    // hi/lo splits of activations + weights
    split_kernel<<<(S * HID / 4 + 255) / 256, 256>>>(hs, hsh, hsl, S * HID);
    split_kernel<<<(HID * QN / 4 + 255) / 256, 256>>>(wq, wqh, wql, HID * QN);
    split_kernel<<<(HID * KVN / 4 + 255) / 256, 256>>>(wk, wkh, wkl, HID * KVN);
    split_kernel<<<(HID * KVN / 4 + 255) / 256, 256>>>(wv, wvh, wvl, HID * KVN);
    split_kernel<<<(QN * HID / 4 + 255) / 256, 256>>>(wo, woh, wol, QN * HID);

    // QKV projections on tensor cores
    gemm3_kernel<<<dim3(QN / 128,  S / 128), 256, GEMM_SMEM_BYTES>>>(
        hsh, hsl, wqh, wql, gq, S, QN, HID);
    gemm3_kernel<<<dim3(KVN / 128, S / 128), 256, GEMM_SMEM_BYTES>>>(
        hsh, hsl, wkh, wkl, gk, S, KVN, HID);
    gemm3_kernel<<<dim3(KVN / 128, S / 128), 256, GEMM_SMEM_BYTES>>>(
        hsh, hsl, wvh, wvl, gv, S, KVN, HID);

    // RMSNorm + RoPE -> bf16 hi/lo attention operands
    norm_rope_kernel<<<dim3(S, 16), 256>>>(gq, gk, gv, cosp, sinp, qw, kw,
                                           qh, ql, kh, kl, vh, vl);

    // Tensor-core attention
    attn_tc_kernel<<<dim3(S / 128, NH), 256, ATT_SM_BYTES>>>(
        qh, ql, kh, kl, vh, vl, ga);

    // Output projection
    split_kernel<<<(S * QN / 4 + 255) / 256, 256>>>(ga, ath, atl, S * QN);
    gemm3_kernel<<<dim3(HID / 128, S / 128), 256, GEMM_SMEM_BYTES>>>(
        ath, atl, woh, wol, out, S, HID, QN);
}

// round 6
// speedup vs baseline: 2.9603x; 1.1149x over previous
#include <cuda_runtime.h>
#include <cuda_fp16.h>
#include <math.h>
#include <stdint.h>

// ---------------- problem constants ----------------
#define S     2048
#define HID   2560
#define NH    8
#define NKV   4
#define DH    256
#define WIN   1024
#define QN    (NH*DH)    // 2048
#define KVN   (NKV*DH)   // 1024

// ---------------- scratch (static device memory) ----------------
__device__ float g_q[S * QN];
__device__ float g_k[S * KVN];
__device__ float g_v[S * KVN];

// hi/lo fp16 splits
__device__ __half g_hs_h[S * HID],  g_hs_l[S * HID];
__device__ __half g_wq_h[HID * QN], g_wq_l[HID * QN];
__device__ __half g_wk_h[HID * KVN], g_wk_l[HID * KVN];
__device__ __half g_wv_h[HID * KVN];                    // 2-pass: hi only
__device__ __half g_wo_h[QN * HID];                     // 2-pass: hi only
__device__ __half g_at_h[S * QN],   g_at_l[S * QN];     // attn out hi/lo

// attention operand splits (post norm+rope)
__device__ __half g_qh[S * QN],  g_ql[S * QN];
__device__ __half g_kh[S * KVN], g_kl[S * KVN];
__device__ __half g_vh[S * KVN];                        // V single fp16

// ---------------- PTX helpers ----------------
#define CP16(dst_u32, src_ptr) \
    asm volatile("cp.async.cg.shared.global [%0], [%1], 16;\n" :: "r"(dst_u32), "l"(src_ptr))
#define CP_COMMIT()  asm volatile("cp.async.commit_group;\n")
#define CP_WAIT0()   asm volatile("cp.async.wait_group 0;\n" ::: "memory")

#define LDSM4(R, addr) \
    asm volatile("ldmatrix.sync.aligned.m8n8.x4.shared.b16 {%0,%1,%2,%3}, [%4];\n" \
        : "=r"((R)[0]), "=r"((R)[1]), "=r"((R)[2]), "=r"((R)[3]) : "r"(addr))
#define LDSM4T(R, addr) \
    asm volatile("ldmatrix.sync.aligned.m8n8.x4.trans.shared.b16 {%0,%1,%2,%3}, [%4];\n" \
        : "=r"((R)[0]), "=r"((R)[1]), "=r"((R)[2]), "=r"((R)[3]) : "r"(addr))

#define MMA_FP16(d, a, b0, b1) \
    asm volatile("mma.sync.aligned.m16n8k16.row.col.f32.f16.f16.f32 " \
        "{%0,%1,%2,%3},{%4,%5,%6,%7},{%8,%9},{%0,%1,%2,%3};\n" \
        : "+f"((d)[0]), "+f"((d)[1]), "+f"((d)[2]), "+f"((d)[3]) \
        : "r"((a)[0]), "r"((a)[1]), "r"((a)[2]), "r"((a)[3]), "r"(b0), "r"(b1))

__device__ __forceinline__ uint32_t smem_u32(const void* p) {
    return (uint32_t)__cvta_generic_to_shared(p);
}
__device__ __forceinline__ uint32_t pack_h2(float a, float b) {
    __half2 h = __halves2half2(__float2half_rn(a), __float2half_rn(b));
    return *(uint32_t*)&h;
}

// =====================================================================
// split fp32 -> (hi, lo) fp16
// =====================================================================
__global__ __launch_bounds__(256) void split_kernel(
    const float* __restrict__ x, __half* __restrict__ h,
    __half* __restrict__ l, int n)
{
    int i = (blockIdx.x * 256 + threadIdx.x) * 4;
    if (i >= n) return;
    float4 v = *(const float4*)(x + i);
    __half h0 = __float2half_rn(v.x), h1 = __float2half_rn(v.y);
    __half h2 = __float2half_rn(v.z), h3 = __float2half_rn(v.w);
    __half l0 = __float2half_rn(v.x - __half2float(h0));
    __half l1 = __float2half_rn(v.y - __half2float(h1));
    __half l2 = __float2half_rn(v.z - __half2float(h2));
    __half l3 = __float2half_rn(v.w - __half2float(h3));
    *(__half2*)(h + i)     = __halves2half2(h0, h1);
    *(__half2*)(h + i + 2) = __halves2half2(h2, h3);
    *(__half2*)(l + i)     = __halves2half2(l0, l1);
    *(__half2*)(l + i + 2) = __halves2half2(l2, l3);
}

// split fp32 -> hi fp16 only (for 2-pass B operands)
__global__ __launch_bounds__(256) void splith_kernel(
    const float* __restrict__ x, __half* __restrict__ h, int n)
{
    int i = (blockIdx.x * 256 + threadIdx.x) * 4;
    if (i >= n) return;
    float4 v = *(const float4*)(x + i);
    *(__half2*)(h + i)     = __halves2half2(__float2half_rn(v.x), __float2half_rn(v.y));
    *(__half2*)(h + i + 2) = __halves2half2(__float2half_rn(v.z), __float2half_rn(v.w));
}

// =====================================================================
// fp16 tensor-core GEMM: PASSES=3: C = AhBh + AhBl + AlBh
//                        PASSES=2: C = AhBh + AlBh  (A exact, B fp16)
// 128x128x32 CTA tile, 8 warps (2x4), warp tile 64x32, cp.async 2-stage.
// =====================================================================
#define AS_STR 40
#define BS_STR 136
#define ABUF   (128 * AS_STR)
#define BBUF   (32 * BS_STR)
#define BUFELEM (2 * ABUF + 2 * BBUF)
#define GEMM_SMEM_BYTES (2 * BUFELEM * 2)

template <int PASSES>
__global__ __launch_bounds__(256) void gemm3_kernel(
    const __half* __restrict__ Ah, const __half* __restrict__ Al,
    const __half* __restrict__ Bh, const __half* __restrict__ Bl,
    float* __restrict__ C, int M, int N, int K)
{
    extern __shared__ __half smbuf[];
    const int t    = threadIdx.x;
    const int lane = t & 31;
    const int wid  = t >> 5;
    const int wm   = wid >> 2;
    const int wn   = wid & 3;
    const int m0   = blockIdx.y * 128;
    const int n0   = blockIdx.x * 128;

    float acc[4][4][4];
#pragma unroll
    for (int mi = 0; mi < 4; mi++)
#pragma unroll
        for (int ni = 0; ni < 4; ni++)
#pragma unroll
            for (int r = 0; r < 4; r++) acc[mi][ni][r] = 0.f;

    uint32_t sbase[2][4];
#pragma unroll
    for (int b = 0; b < 2; b++) {
        __half* p = smbuf + b * BUFELEM;
        sbase[b][0] = smem_u32(p);
        sbase[b][1] = smem_u32(p + ABUF);
        sbase[b][2] = smem_u32(p + 2 * ABUF);
        sbase[b][3] = smem_u32(p + 2 * ABUF + BBUF);
    }

    auto issue = [&](int k0, int buf) {
#pragma unroll
        for (int p = 0; p < 2; p++) {
            int id = t + p * 256;
            int am = id >> 2, ac = (id & 3) * 8;
            size_t aoff = (size_t)(m0 + am) * K + k0 + ac;
            uint32_t ad = (uint32_t)(am * AS_STR + ac) * 2;
            CP16(sbase[buf][0] + ad, Ah + aoff);
            CP16(sbase[buf][1] + ad, Al + aoff);
            int bk = id >> 4, bc = (id & 15) * 8;
            size_t boff = (size_t)(k0 + bk) * N + n0 + bc;
            uint32_t bd = (uint32_t)(bk * BS_STR + bc) * 2;
            CP16(sbase[buf][2] + bd, Bh + boff);
            if (PASSES == 3) CP16(sbase[buf][3] + bd, Bl + boff);
        }
        CP_COMMIT();
    };

    issue(0, 0);
    const int nIter = K / 32;

    for (int it = 0; it < nIter; it++) {
        CP_WAIT0();
        __syncthreads();
        if (it + 1 < nIter) issue((it + 1) * 32, (it + 1) & 1);

        const int buf = it & 1;
        const uint32_t ah_s = sbase[buf][0];
        const uint32_t al_s = sbase[buf][1];
        const uint32_t bh_s = sbase[buf][2];
        const uint32_t bl_s = sbase[buf][3];

#pragma unroll
        for (int ks = 0; ks < 32; ks += 16) {
            uint32_t fah[4][4], fal[4][4], fbh[2][4], fbl[2][4];

            int arow = lane & 15;
            int acol = ks + ((lane >> 4) & 1) * 8;
#pragma unroll
            for (int mi = 0; mi < 4; mi++) {
                uint32_t off = (uint32_t)((wm * 64 + mi * 16 + arow) * AS_STR + acol) * 2;
                LDSM4(fah[mi], ah_s + off);
                LDSM4(fal[mi], al_s + off);
            }

            int bkrow = ks + (lane & 7) + ((lane >> 3) & 1) * 8;
#pragma unroll
            for (int np = 0; np < 2; np++) {
                int bcol = wn * 32 + np * 16 + ((lane >> 4) & 1) * 8;
                uint32_t off = (uint32_t)(bkrow * BS_STR + bcol) * 2;
                LDSM4T(fbh[np], bh_s + off);
                if (PASSES == 3) LDSM4T(fbl[np], bl_s + off);
            }

#pragma unroll
            for (int mi = 0; mi < 4; mi++)
#pragma unroll
                for (int ni = 0; ni < 4; ni++) {
                    const uint32_t* bh2 = &fbh[ni >> 1][(ni & 1) * 2];
                    MMA_FP16(acc[mi][ni], fah[mi], bh2[0], bh2[1]);
                    MMA_FP16(acc[mi][ni], fal[mi], bh2[0], bh2[1]);
                    if (PASSES == 3) {
                        const uint32_t* bl2 = &fbl[ni >> 1][(ni & 1) * 2];
                        MMA_FP16(acc[mi][ni], fah[mi], bl2[0], bl2[1]);
                    }
                }
        }
        __syncthreads();
    }

    int g  = lane >> 2;
    int c2 = (lane & 3) * 2;
#pragma unroll
    for (int mi = 0; mi < 4; mi++)
#pragma unroll
        for (int ni = 0; ni < 4; ni++) {
            int row = m0 + wm * 64 + mi * 16 + g;
            int col = n0 + wn * 32 + ni * 8 + c2;
            float2 v0 = make_float2(acc[mi][ni][0], acc[mi][ni][1]);
            float2 v1 = make_float2(acc[mi][ni][2], acc[mi][ni][3]);
            *(float2*)(C + (size_t)row * N + col)       = v0;
            *(float2*)(C + (size_t)(row + 8) * N + col) = v1;
        }
}

// =====================================================================
// Fused RMSNorm (+weight) + RoPE, emitting fp16 operands.
// q,k: hi/lo ; v: hi only.
// =====================================================================
__global__ __launch_bounds__(256) void norm_rope_kernel(
    const float* __restrict__ q, const float* __restrict__ k, const float* __restrict__ v,
    const float* __restrict__ cosp, const float* __restrict__ sinp,
    const float* __restrict__ qw, const float* __restrict__ kw,
    __half* __restrict__ qh, __half* __restrict__ ql,
    __half* __restrict__ kh, __half* __restrict__ kl,
    __half* __restrict__ vh)
{
    const int s   = blockIdx.x;
    const int idx = blockIdx.y;
    const int d   = threadIdx.x;

    const float* base;
    const float* w;
    __half *oh, *ol;
    bool rope;
    if (idx < 8) {
        base = q + (size_t)s * QN + idx * DH; w = qw; rope = true;
        oh = qh + (size_t)s * QN + idx * DH; ol = ql + (size_t)s * QN + idx * DH;
    } else if (idx < 12) {
        base = k + (size_t)s * KVN + (idx - 8) * DH; w = kw; rope = true;
        oh = kh + (size_t)s * KVN + (idx - 8) * DH; ol = kl + (size_t)s * KVN + (idx - 8) * DH;
    } else {
        base = v + (size_t)s * KVN + (idx - 12) * DH; w = nullptr; rope = false;
        oh = vh + (size_t)s * KVN + (idx - 12) * DH; ol = nullptr;
    }

    float x = base[d];
    float ss = x * x;
#pragma unroll
    for (int o = 16; o; o >>= 1) ss += __shfl_xor_sync(0xffffffffu, ss, o);

    __shared__ float wsum[8];
    if ((d & 31) == 0) wsum[d >> 5] = ss;
    __syncthreads();
    float tot = 0.f;
#pragma unroll
    for (int i = 0; i < 8; i++) tot += wsum[i];

    float inv = rsqrtf(tot * (1.0f / 256.0f) + 1e-6f);
    float y = x * inv;
    if (w) y *= w[d];

    __shared__ float sh[256];
    sh[d] = y;
    __syncthreads();

    float out = y;
    if (rope) {
        float c  = cosp[(size_t)s * DH + d];
        float si = sinp[(size_t)s * DH + d];
        float rh = (d < 128) ? -sh[d + 128] : sh[d - 128];
        out = y * c + rh * si;
    }
    __half hb = __float2half_rn(out);
    oh[d] = hb;
    if (ol) ol[d] = __float2half_rn(out - __half2float(hb));
}

// =====================================================================
// Tensor-core flash attention (fp16), sliding-window causal.
// QK^T: 3-pass (q hi/lo, k hi/lo). PV: 2-pass (P hi/lo x V hi).
// Emits attention output directly as fp16 hi/lo for the wo GEMM.
// =====================================================================
#define KT    32
#define ASTR  264
#define ATT_SM_ELEM (2*128*ASTR + 3*KT*ASTR)
#define ATT_SM_BYTES (ATT_SM_ELEM * 2)

__global__ __launch_bounds__(256, 1) void attn_tc_kernel(
    const __half* __restrict__ Qh, const __half* __restrict__ Ql,
    const __half* __restrict__ Kh, const __half* __restrict__ Kl,
    const __half* __restrict__ Vh,
    __half* __restrict__ Oh, __half* __restrict__ Ol)
{
    extern __shared__ __half sm2[];
    const int t    = threadIdx.x;
    const int lane = t & 31;
    const int w    = t >> 5;
    const int q0   = blockIdx.x * 128;
    const int h    = blockIdx.y;
    const int kvh  = h >> 1;

    const uint32_t sQh = smem_u32(sm2);
    const uint32_t sQl = sQh + 128 * ASTR * 2;
    const uint32_t sKh = sQl + 128 * ASTR * 2;
    const uint32_t sKl = sKh + KT * ASTR * 2;
    const uint32_t sVh = sKl + KT * ASTR * 2;

    const __half* gqh = Qh + (size_t)q0 * QN + h * DH;
    const __half* gql = Ql + (size_t)q0 * QN + h * DH;
#pragma unroll
    for (int it = 0; it < 16; it++) {
        int id = t + it * 256;
        int row = id >> 5, ch = id & 31;
        uint32_t d = (uint32_t)(row * ASTR + ch * 8) * 2;
        size_t g = (size_t)row * QN + ch * 8;
        CP16(sQh + d, gqh + g);
        CP16(sQl + d, gql + g);
    }
    CP_COMMIT();

    float o[32][4];
#pragma unroll
    for (int dt = 0; dt < 32; dt++)
#pragma unroll
        for (int r = 0; r < 4; r++) o[dt][r] = 0.f;
    float mrow[2] = {-1e30f, -1e30f};
    float lrow[2] = {0.f, 0.f};

    CP_WAIT0();
    __syncthreads();

    const int kb_lo = max(0, q0 - (WIN - 1)) >> 5;
    const int kb_hi = (q0 + 127) >> 5;
    const int qw_lo = q0 + w * 16;
    const int gq_row = lane >> 2;
    const int t4 = lane & 3;

    for (int kb = kb_lo; kb <= kb_hi; kb++) {
        const int k0 = kb * KT;
        __syncthreads();

        {
            const __half* gkh = Kh + (size_t)k0 * KVN + kvh * DH;
            const __half* gkl = Kl + (size_t)k0 * KVN + kvh * DH;
            const __half* gvh = Vh + (size_t)k0 * KVN + kvh * DH;
#pragma unroll
            for (int it = 0; it < 4; it++) {
                int id = t + it * 256;
                int row = id >> 5, ch = id & 31;
                uint32_t d = (uint32_t)(row * ASTR + ch * 8) * 2;
                size_t g = (size_t)row * KVN + ch * 8;
                CP16(sKh + d, gkh + g);
                CP16(sKl + d, gkl + g);
                CP16(sVh + d, gvh + g);
            }
        }
        CP_COMMIT();
        CP_WAIT0();
        __syncthreads();

        bool active = (k0 <= qw_lo + 15) && (k0 + KT - 1 >= qw_lo - (WIN - 1));
        if (!active) continue;

        float s[4][4];
#pragma unroll
        for (int tl = 0; tl < 4; tl++)
#pragma unroll
            for (int r = 0; r < 4; r++) s[tl][r] = 0.f;

#pragma unroll
        for (int dc = 0; dc < 16; dc++) {
            uint32_t qa[4], qb[4], k1h[4], k2h[4], k1l[4], k2l[4];
            uint32_t qoff = (uint32_t)((w * 16 + (lane & 15)) * ASTR + dc * 16 + (lane >> 4) * 8) * 2;
            LDSM4(qa, sQh + qoff);
            LDSM4(qb, sQl + qoff);
            uint32_t koff = (uint32_t)((lane & 15) * ASTR + dc * 16 + (lane >> 4) * 8) * 2;
            LDSM4(k1h, sKh + koff);
            LDSM4(k2h, sKh + koff + 16 * ASTR * 2);
            LDSM4(k1l, sKl + koff);
            LDSM4(k2l, sKl + koff + 16 * ASTR * 2);

            MMA_FP16(s[0], qa, k1h[0], k1h[2]);
            MMA_FP16(s[1], qa, k1h[1], k1h[3]);
            MMA_FP16(s[2], qa, k2h[0], k2h[2]);
            MMA_FP16(s[3], qa, k2h[1], k2h[3]);
            MMA_FP16(s[0], qa, k1l[0], k1l[2]);
            MMA_FP16(s[1], qa, k1l[1], k1l[3]);
            MMA_FP16(s[2], qa, k2l[0], k2l[2]);
            MMA_FP16(s[3], qa, k2l[1], k2l[3]);
            MMA_FP16(s[0], qb, k1h[0], k1h[2]);
            MMA_FP16(s[1], qb, k1h[1], k1h[3]);
            MMA_FP16(s[2], qb, k2h[0], k2h[2]);
            MMA_FP16(s[3], qb, k2h[1], k2h[3]);
        }

        float corr[2];
#pragma unroll
        for (int r = 0; r < 2; r++) {
            int qg = qw_lo + gq_row + r * 8;
            float mx = -1e30f;
#pragma unroll
            for (int tl = 0; tl < 4; tl++) {
#pragma unroll
                for (int c = 0; c < 2; c++) {
                    int kg = k0 + tl * 8 + 2 * t4 + c;
                    bool ok = (kg <= qg) && (qg - kg < WIN);
                    if (!ok) s[tl][r * 2 + c] = -1e30f;
                    mx = fmaxf(mx, s[tl][r * 2 + c]);
                }
            }
            mx = fmaxf(mx, __shfl_xor_sync(0xffffffffu, mx, 1));
            mx = fmaxf(mx, __shfl_xor_sync(0xffffffffu, mx, 2));
            float m_new = fmaxf(mrow[r], mx);
            float mexp = (m_new <= -1e29f) ? 0.f : m_new;
            float sum = 0.f;
#pragma unroll
            for (int tl = 0; tl < 4; tl++) {
#pragma unroll
                for (int c = 0; c < 2; c++) {
                    float p = __expf(s[tl][r * 2 + c] - mexp);
                    s[tl][r * 2 + c] = p;
                    sum += p;
                }
            }
            sum += __shfl_xor_sync(0xffffffffu, sum, 1);
            sum += __shfl_xor_sync(0xffffffffu, sum, 2);
            corr[r] = __expf(mrow[r] - m_new);
            mrow[r] = m_new;
            lrow[r] = lrow[r] * corr[r] + sum;
        }

        // P -> fp16 hi/lo A-fragments
        uint32_t ph[2][4], pl[2][4];
#pragma unroll
        for (int kc = 0; kc < 2; kc++) {
#pragma unroll
            for (int r2 = 0; r2 < 4; r2++) {
                int tl = kc * 2 + (r2 >> 1);
                int r  = r2 & 1;
                float p0 = s[tl][r * 2 + 0];
                float p1 = s[tl][r * 2 + 1];
                __half h0 = __float2half_rn(p0);
                __half h1 = __float2half_rn(p1);
                __half2 hh = __halves2half2(h0, h1);
                __half2 ll = __halves2half2(__float2half_rn(p0 - __half2float(h0)),
                                            __float2half_rn(p1 - __half2float(h1)));
                ph[kc][r2] = *(uint32_t*)&hh;
                pl[kc][r2] = *(uint32_t*)&ll;
            }
        }

#pragma unroll
        for (int dt = 0; dt < 32; dt++) {
            o[dt][0] *= corr[0]; o[dt][1] *= corr[0];
            o[dt][2] *= corr[1]; o[dt][3] *= corr[1];
        }

        // PV: 2-pass (P exact, V fp16)
#pragma unroll
        for (int dg = 0; dg < 16; dg++) {
#pragma unroll
            for (int kc = 0; kc < 2; kc++) {
                uint32_t vh4[4];
                uint32_t voff = (uint32_t)((kc * 16 + (lane & 7) + ((lane >> 3) & 1) * 8) * ASTR
                                           + dg * 16 + ((lane >> 4) & 1) * 8) * 2;
                LDSM4T(vh4, sVh + voff);
                MMA_FP16(o[2 * dg],     ph[kc], vh4[0], vh4[1]);
                MMA_FP16(o[2 * dg + 1], ph[kc], vh4[2], vh4[3]);
                MMA_FP16(o[2 * dg],     pl[kc], vh4[0], vh4[1]);
                MMA_FP16(o[2 * dg + 1], pl[kc], vh4[2], vh4[3]);
            }
        }
    }

    // finalize -> fp16 hi/lo output (A operand of wo GEMM)
    float inv0 = 1.f / lrow[0];
    float inv1 = 1.f / lrow[1];
    size_t r0 = (size_t)(q0 + w * 16 + gq_row) * QN + h * DH;
    size_t r1 = r0 + (size_t)8 * QN;
#pragma unroll
    for (int dt = 0; dt < 32; dt++) {
        int col = dt * 8 + 2 * t4;
        float a0 = o[dt][0] * inv0, a1 = o[dt][1] * inv0;
        float b0 = o[dt][2] * inv1, b1 = o[dt][3] * inv1;
        __half ha0 = __float2half_rn(a0), ha1 = __float2half_rn(a1);
        __half hb0 = __float2half_rn(b0), hb1 = __float2half_rn(b1);
        *(__half2*)(Oh + r0 + col) = __halves2half2(ha0, ha1);
        *(__half2*)(Oh + r1 + col) = __halves2half2(hb0, hb1);
        *(__half2*)(Ol + r0 + col) = __halves2half2(
            __float2half_rn(a0 - __half2float(ha0)), __float2half_rn(a1 - __half2float(ha1)));
        *(__half2*)(Ol + r1 + col) = __halves2half2(
            __float2half_rn(b0 - __half2float(hb0)), __float2half_rn(b1 - __half2float(hb1)));
    }
}

// =====================================================================
// kernel_launch
// =====================================================================
extern "C" void kernel_launch(void* const* d_in, const int* in_sizes, int n_in,
                              void* d_out, int out_size)
{
    const float* hs   = (const float*)d_in[0];
    const float* cosp = (const float*)d_in[1];
    const float* sinp = (const float*)d_in[2];
    const float* wq   = (const float*)d_in[3];
    const float* wk   = (const float*)d_in[4];
    const float* wv   = (const float*)d_in[5];
    const float* wo   = (const float*)d_in[6];
    const float* qw   = (const float*)d_in[7];
    const float* kw   = (const float*)d_in[8];
    float* out = (float*)d_out;

    float *gq, *gk, *gv;
    cudaGetSymbolAddress((void**)&gq, g_q);
    cudaGetSymbolAddress((void**)&gk, g_k);
    cudaGetSymbolAddress((void**)&gv, g_v);

    __half *hsh, *hsl, *wqh, *wql, *wkh, *wkl, *wvh, *woh, *ath, *atl;
    __half *qh, *ql, *kh, *kl, *vh;
    cudaGetSymbolAddress((void**)&hsh, g_hs_h); cudaGetSymbolAddress((void**)&hsl, g_hs_l);
    cudaGetSymbolAddress((void**)&wqh, g_wq_h); cudaGetSymbolAddress((void**)&wql, g_wq_l);
    cudaGetSymbolAddress((void**)&wkh, g_wk_h); cudaGetSymbolAddress((void**)&wkl, g_wk_l);
    cudaGetSymbolAddress((void**)&wvh, g_wv_h);
    cudaGetSymbolAddress((void**)&woh, g_wo_h);
    cudaGetSymbolAddress((void**)&ath, g_at_h); cudaGetSymbolAddress((void**)&atl, g_at_l);
    cudaGetSymbolAddress((void**)&qh, g_qh);    cudaGetSymbolAddress((void**)&ql, g_ql);
    cudaGetSymbolAddress((void**)&kh, g_kh);    cudaGetSymbolAddress((void**)&kl, g_kl);
    cudaGetSymbolAddress((void**)&vh, g_vh);

    cudaFuncSetAttribute(gemm3_kernel<3>, cudaFuncAttributeMaxDynamicSharedMemorySize,
                         GEMM_SMEM_BYTES);
    cudaFuncSetAttribute(gemm3_kernel<2>, cudaFuncAttributeMaxDynamicSharedMemorySize,
                         GEMM_SMEM_BYTES);
    cudaFuncSetAttribute(attn_tc_kernel, cudaFuncAttributeMaxDynamicSharedMemorySize,
                         ATT_SM_BYTES);

    // splits
    split_kernel<<<(S * HID / 4 + 255) / 256, 256>>>(hs, hsh, hsl, S * HID);
    split_kernel<<<(HID * QN / 4 + 255) / 256, 256>>>(wq, wqh, wql, HID * QN);
    split_kernel<<<(HID * KVN / 4 + 255) / 256, 256>>>(wk, wkh, wkl, HID * KVN);
    splith_kernel<<<(HID * KVN / 4 + 255) / 256, 256>>>(wv, wvh, HID * KVN);
    splith_kernel<<<(QN * HID / 4 + 255) / 256, 256>>>(wo, woh, QN * HID);

    // projections: q,k 3-pass; v 2-pass
    gemm3_kernel<3><<<dim3(QN / 128,  S / 128), 256, GEMM_SMEM_BYTES>>>(
        hsh, hsl, wqh, wql, gq, S, QN, HID);
    gemm3_kernel<3><<<dim3(KVN / 128, S / 128), 256, GEMM_SMEM_BYTES>>>(
        hsh, hsl, wkh, wkl, gk, S, KVN, HID);
    gemm3_kernel<2><<<dim3(KVN / 128, S / 128), 256, GEMM_SMEM_BYTES>>>(
        hsh, hsl, wvh, wvh, gv, S, KVN, HID);

    // RMSNorm + RoPE -> fp16 attention operands
    norm_rope_kernel<<<dim3(S, 16), 256>>>(gq, gk, gv, cosp, sinp, qw, kw,
                                           qh, ql, kh, kl, vh);

    // attention (emits fp16 hi/lo output)
    attn_tc_kernel<<<dim3(S / 128, NH), 256, ATT_SM_BYTES>>>(
        qh, ql, kh, kl, vh, ath, atl);

    // output projection: 2-pass
    gemm3_kernel<2><<<dim3(HID / 128, S / 128), 256, GEMM_SMEM_BYTES>>>(
        ath, atl, woh, woh, out, S, HID, QN);
}

// round 7
// speedup vs baseline: 3.0203x; 1.0203x over previous
#include <cuda_runtime.h>
#include <cuda_fp16.h>
#include <math.h>
#include <stdint.h>

// ---------------- problem constants ----------------
#define S     2048
#define HID   2560
#define NH    8
#define NKV   4
#define DH    256
#define WIN   1024
#define QN    (NH*DH)    // 2048
#define KVN   (NKV*DH)   // 1024

// ---------------- scratch ----------------
__device__ float g_q[S * QN];
__device__ float g_k[S * KVN];
__device__ float g_v[S * KVN];

__device__ __half g_hs_h[S * HID],  g_hs_l[S * HID];
__device__ __half g_wq_h[HID * QN], g_wq_l[HID * QN];
__device__ __half g_wk_h[HID * KVN], g_wk_l[HID * KVN];
__device__ __half g_wv_h[HID * KVN];
__device__ __half g_wo_h[QN * HID];
__device__ __half g_at_h[S * QN],   g_at_l[S * QN];

__device__ __half g_qh[S * QN],  g_ql[S * QN];
__device__ __half g_kh[S * KVN], g_kl[S * KVN];
__device__ __half g_vh[S * KVN];

// ---------------- PTX helpers ----------------
#define CP16(dst_u32, src_ptr) \
    asm volatile("cp.async.cg.shared.global [%0], [%1], 16;\n" :: "r"(dst_u32), "l"(src_ptr))
#define CP_COMMIT()  asm volatile("cp.async.commit_group;\n")
#define CP_WAIT0()   asm volatile("cp.async.wait_group 0;\n" ::: "memory")

#define LDSM4(R, addr) \
    asm volatile("ldmatrix.sync.aligned.m8n8.x4.shared.b16 {%0,%1,%2,%3}, [%4];\n" \
        : "=r"((R)[0]), "=r"((R)[1]), "=r"((R)[2]), "=r"((R)[3]) : "r"(addr))
#define LDSM4T(R, addr) \
    asm volatile("ldmatrix.sync.aligned.m8n8.x4.trans.shared.b16 {%0,%1,%2,%3}, [%4];\n" \
        : "=r"((R)[0]), "=r"((R)[1]), "=r"((R)[2]), "=r"((R)[3]) : "r"(addr))

// fp32-accumulate MMA
#define MMA_FP16(d, a, b0, b1) \
    asm volatile("mma.sync.aligned.m16n8k16.row.col.f32.f16.f16.f32 " \
        "{%0,%1,%2,%3},{%4,%5,%6,%7},{%8,%9},{%0,%1,%2,%3};\n" \
        : "+f"((d)[0]), "+f"((d)[1]), "+f"((d)[2]), "+f"((d)[3]) \
        : "r"((a)[0]), "r"((a)[1]), "r"((a)[2]), "r"((a)[3]), "r"(b0), "r"(b1))

// fp16-accumulate MMA (packed half2 accumulators, 2 regs)
#define MMA_F16A(d, a, b0, b1) \
    asm volatile("mma.sync.aligned.m16n8k16.row.col.f16.f16.f16.f16 " \
        "{%0,%1},{%2,%3,%4,%5},{%6,%7},{%0,%1};\n" \
        : "+r"((d)[0]), "+r"((d)[1]) \
        : "r"((a)[0]), "r"((a)[1]), "r"((a)[2]), "r"((a)[3]), "r"(b0), "r"(b1))

__device__ __forceinline__ uint32_t smem_u32(const void* p) {
    return (uint32_t)__cvta_generic_to_shared(p);
}
__device__ __forceinline__ void add_h2(float* f01, uint32_t packed) {
    __half2 h = *(__half2*)&packed;
    float2 v = __half22float2(h);
    f01[0] += v.x; f01[1] += v.y;
}

// =====================================================================
// splits
// =====================================================================
__global__ __launch_bounds__(256) void split_kernel(
    const float* __restrict__ x, __half* __restrict__ h,
    __half* __restrict__ l, int n)
{
    int i = (blockIdx.x * 256 + threadIdx.x) * 4;
    if (i >= n) return;
    float4 v = *(const float4*)(x + i);
    __half h0 = __float2half_rn(v.x), h1 = __float2half_rn(v.y);
    __half h2 = __float2half_rn(v.z), h3 = __float2half_rn(v.w);
    *(__half2*)(h + i)     = __halves2half2(h0, h1);
    *(__half2*)(h + i + 2) = __halves2half2(h2, h3);
    *(__half2*)(l + i)     = __halves2half2(
        __float2half_rn(v.x - __half2float(h0)), __float2half_rn(v.y - __half2float(h1)));
    *(__half2*)(l + i + 2) = __halves2half2(
        __float2half_rn(v.z - __half2float(h2)), __float2half_rn(v.w - __half2float(h3)));
}

__global__ __launch_bounds__(256) void splith_kernel(
    const float* __restrict__ x, __half* __restrict__ h, int n)
{
    int i = (blockIdx.x * 256 + threadIdx.x) * 4;
    if (i >= n) return;
    float4 v = *(const float4*)(x + i);
    *(__half2*)(h + i)     = __halves2half2(__float2half_rn(v.x), __float2half_rn(v.y));
    *(__half2*)(h + i + 2) = __halves2half2(__float2half_rn(v.z), __float2half_rn(v.w));
}

// =====================================================================
// fp16 TC GEMM. PASSES=3: C = AhBh(f32acc) + [AhBl + AlBh](f16acc)
//              PASSES=2: C = AhBh(f32acc) + [AlBh](f16acc)
// =====================================================================
#define AS_STR 40
#define BS_STR 136
#define ABUF   (128 * AS_STR)
#define BBUF   (32 * BS_STR)
#define BUFELEM (2 * ABUF + 2 * BBUF)
#define GEMM_SMEM_BYTES (2 * BUFELEM * 2)

template <int PASSES>
__global__ __launch_bounds__(256) void gemm3_kernel(
    const __half* __restrict__ Ah, const __half* __restrict__ Al,
    const __half* __restrict__ Bh, const __half* __restrict__ Bl,
    float* __restrict__ C, int M, int N, int K)
{
    extern __shared__ __half smbuf[];
    const int t    = threadIdx.x;
    const int lane = t & 31;
    const int wid  = t >> 5;
    const int wm   = wid >> 2;
    const int wn   = wid & 3;
    const int m0   = blockIdx.y * 128;
    const int n0   = blockIdx.x * 128;

    float acc[4][4][4];
    uint32_t accL[4][4][2];
#pragma unroll
    for (int mi = 0; mi < 4; mi++)
#pragma unroll
        for (int ni = 0; ni < 4; ni++) {
#pragma unroll
            for (int r = 0; r < 4; r++) acc[mi][ni][r] = 0.f;
            accL[mi][ni][0] = 0u; accL[mi][ni][1] = 0u;
        }

    uint32_t sbase[2][4];
#pragma unroll
    for (int b = 0; b < 2; b++) {
        __half* p = smbuf + b * BUFELEM;
        sbase[b][0] = smem_u32(p);
        sbase[b][1] = smem_u32(p + ABUF);
        sbase[b][2] = smem_u32(p + 2 * ABUF);
        sbase[b][3] = smem_u32(p + 2 * ABUF + BBUF);
    }

    auto issue = [&](int k0, int buf) {
#pragma unroll
        for (int p = 0; p < 2; p++) {
            int id = t + p * 256;
            int am = id >> 2, ac = (id & 3) * 8;
            size_t aoff = (size_t)(m0 + am) * K + k0 + ac;
            uint32_t ad = (uint32_t)(am * AS_STR + ac) * 2;
            CP16(sbase[buf][0] + ad, Ah + aoff);
            CP16(sbase[buf][1] + ad, Al + aoff);
            int bk = id >> 4, bc = (id & 15) * 8;
            size_t boff = (size_t)(k0 + bk) * N + n0 + bc;
            uint32_t bd = (uint32_t)(bk * BS_STR + bc) * 2;
            CP16(sbase[buf][2] + bd, Bh + boff);
            if (PASSES == 3) CP16(sbase[buf][3] + bd, Bl + boff);
        }
        CP_COMMIT();
    };

    issue(0, 0);
    const int nIter = K / 32;

    for (int it = 0; it < nIter; it++) {
        CP_WAIT0();
        __syncthreads();
        if (it + 1 < nIter) issue((it + 1) * 32, (it + 1) & 1);

        const int buf = it & 1;
        const uint32_t ah_s = sbase[buf][0];
        const uint32_t al_s = sbase[buf][1];
        const uint32_t bh_s = sbase[buf][2];
        const uint32_t bl_s = sbase[buf][3];

#pragma unroll
        for (int ks = 0; ks < 32; ks += 16) {
            uint32_t fah[4][4], fal[4][4], fbh[2][4], fbl[2][4];

            int arow = lane & 15;
            int acol = ks + ((lane >> 4) & 1) * 8;
#pragma unroll
            for (int mi = 0; mi < 4; mi++) {
                uint32_t off = (uint32_t)((wm * 64 + mi * 16 + arow) * AS_STR + acol) * 2;
                LDSM4(fah[mi], ah_s + off);
                LDSM4(fal[mi], al_s + off);
            }

            int bkrow = ks + (lane & 7) + ((lane >> 3) & 1) * 8;
#pragma unroll
            for (int np = 0; np < 2; np++) {
                int bcol = wn * 32 + np * 16 + ((lane >> 4) & 1) * 8;
                uint32_t off = (uint32_t)(bkrow * BS_STR + bcol) * 2;
                LDSM4T(fbh[np], bh_s + off);
                if (PASSES == 3) LDSM4T(fbl[np], bl_s + off);
            }

#pragma unroll
            for (int mi = 0; mi < 4; mi++)
#pragma unroll
                for (int ni = 0; ni < 4; ni++) {
                    const uint32_t* bh2 = &fbh[ni >> 1][(ni & 1) * 2];
                    MMA_FP16(acc[mi][ni], fah[mi], bh2[0], bh2[1]);      // hi: f32 acc
                    MMA_F16A(accL[mi][ni], fal[mi], bh2[0], bh2[1]);     // cross: f16 acc
                    if (PASSES == 3) {
                        const uint32_t* bl2 = &fbl[ni >> 1][(ni & 1) * 2];
                        MMA_F16A(accL[mi][ni], fah[mi], bl2[0], bl2[1]); // cross: f16 acc
                    }
                }
        }
        __syncthreads();
    }

    int g  = lane >> 2;
    int c2 = (lane & 3) * 2;
#pragma unroll
    for (int mi = 0; mi < 4; mi++)
#pragma unroll
        for (int ni = 0; ni < 4; ni++) {
            add_h2(&acc[mi][ni][0], accL[mi][ni][0]);
            add_h2(&acc[mi][ni][2], accL[mi][ni][1]);
            int row = m0 + wm * 64 + mi * 16 + g;
            int col = n0 + wn * 32 + ni * 8 + c2;
            *(float2*)(C + (size_t)row * N + col)       = make_float2(acc[mi][ni][0], acc[mi][ni][1]);
            *(float2*)(C + (size_t)(row + 8) * N + col) = make_float2(acc[mi][ni][2], acc[mi][ni][3]);
        }
}

// =====================================================================
// Fused RMSNorm (+weight) + RoPE — warp-per-head, no smem, no block sync.
// block = 8 warps; warp handles one (s, idx) row of 256 elems (8/lane).
// =====================================================================
__global__ __launch_bounds__(256) void norm_rope_kernel(
    const float* __restrict__ q, const float* __restrict__ k, const float* __restrict__ v,
    const float* __restrict__ cosp, const float* __restrict__ sinp,
    const float* __restrict__ qw, const float* __restrict__ kw,
    __half* __restrict__ qh, __half* __restrict__ ql,
    __half* __restrict__ kh, __half* __restrict__ kl,
    __half* __restrict__ vh)
{
    const int lane = threadIdx.x & 31;
    const int row  = blockIdx.x * 8 + (threadIdx.x >> 5);   // 0 .. S*16-1
    const int s    = row >> 4;
    const int idx  = row & 15;

    const float* base;
    const float* w;
    __half *oh, *ol;
    bool rope;
    if (idx < 8) {
        base = q + (size_t)s * QN + idx * DH; w = qw; rope = true;
        oh = qh + (size_t)s * QN + idx * DH; ol = ql + (size_t)s * QN + idx * DH;
    } else if (idx < 12) {
        base = k + (size_t)s * KVN + (idx - 8) * DH; w = kw; rope = true;
        oh = kh + (size_t)s * KVN + (idx - 8) * DH; ol = kl + (size_t)s * KVN + (idx - 8) * DH;
    } else {
        base = v + (size_t)s * KVN + (idx - 12) * DH; w = nullptr; rope = false;
        oh = vh + (size_t)s * KVN + (idx - 12) * DH; ol = nullptr;
    }

    const int d0 = lane * 8;
    float x[8];
    *(float4*)&x[0] = *(const float4*)(base + d0);
    *(float4*)&x[4] = *(const float4*)(base + d0 + 4);

    float ss = 0.f;
#pragma unroll
    for (int j = 0; j < 8; j++) ss += x[j] * x[j];
#pragma unroll
    for (int o = 16; o; o >>= 1) ss += __shfl_xor_sync(0xffffffffu, ss, o);

    float inv = rsqrtf(ss * (1.0f / 256.0f) + 1e-6f);
    float y[8];
#pragma unroll
    for (int j = 0; j < 8; j++) y[j] = x[j] * inv;
    if (w) {
        float wv[8];
        *(float4*)&wv[0] = *(const float4*)(w + d0);
        *(float4*)&wv[4] = *(const float4*)(w + d0 + 4);
#pragma unroll
        for (int j = 0; j < 8; j++) y[j] *= wv[j];
    }

    float out[8];
    if (rope) {
        float c[8], si[8];
        *(float4*)&c[0]  = *(const float4*)(cosp + (size_t)s * DH + d0);
        *(float4*)&c[4]  = *(const float4*)(cosp + (size_t)s * DH + d0 + 4);
        *(float4*)&si[0] = *(const float4*)(sinp + (size_t)s * DH + d0);
        *(float4*)&si[4] = *(const float4*)(sinp + (size_t)s * DH + d0 + 4);
#pragma unroll
        for (int j = 0; j < 8; j++) {
            float pv = __shfl_xor_sync(0xffffffffu, y[j], 16);   // y[d +/- 128]
            float rh = (lane < 16) ? -pv : pv;
            out[j] = y[j] * c[j] + rh * si[j];
        }
    } else {
#pragma unroll
        for (int j = 0; j < 8; j++) out[j] = y[j];
    }

    __half hi8[8], lo8[8];
#pragma unroll
    for (int j = 0; j < 8; j++) {
        hi8[j] = __float2half_rn(out[j]);
        lo8[j] = __float2half_rn(out[j] - __half2float(hi8[j]));
    }
    *(uint4*)(oh + d0) = *(uint4*)hi8;
    if (ol) *(uint4*)(ol + d0) = *(uint4*)lo8;
}

// =====================================================================
// TC flash attention. QK^T: hi f32acc + 2 cross f16acc. PV: 2x f32acc.
// =====================================================================
#define KT    32
#define ASTR  264
#define ATT_SM_ELEM (2*128*ASTR + 3*KT*ASTR)
#define ATT_SM_BYTES (ATT_SM_ELEM * 2)

__global__ __launch_bounds__(256, 1) void attn_tc_kernel(
    const __half* __restrict__ Qh, const __half* __restrict__ Ql,
    const __half* __restrict__ Kh, const __half* __restrict__ Kl,
    const __half* __restrict__ Vh,
    __half* __restrict__ Oh, __half* __restrict__ Ol)
{
    extern __shared__ __half sm2[];
    const int t    = threadIdx.x;
    const int lane = t & 31;
    const int w    = t >> 5;
    const int q0   = blockIdx.x * 128;
    const int h    = blockIdx.y;
    const int kvh  = h >> 1;

    const uint32_t sQh = smem_u32(sm2);
    const uint32_t sQl = sQh + 128 * ASTR * 2;
    const uint32_t sKh = sQl + 128 * ASTR * 2;
    const uint32_t sKl = sKh + KT * ASTR * 2;
    const uint32_t sVh = sKl + KT * ASTR * 2;

    const __half* gqh = Qh + (size_t)q0 * QN + h * DH;
    const __half* gql = Ql + (size_t)q0 * QN + h * DH;
#pragma unroll
    for (int it = 0; it < 16; it++) {
        int id = t + it * 256;
        int row = id >> 5, ch = id & 31;
        uint32_t d = (uint32_t)(row * ASTR + ch * 8) * 2;
        size_t g = (size_t)row * QN + ch * 8;
        CP16(sQh + d, gqh + g);
        CP16(sQl + d, gql + g);
    }
    CP_COMMIT();

    float o[32][4];
#pragma unroll
    for (int dt = 0; dt < 32; dt++)
#pragma unroll
        for (int r = 0; r < 4; r++) o[dt][r] = 0.f;
    float mrow[2] = {-1e30f, -1e30f};
    float lrow[2] = {0.f, 0.f};

    CP_WAIT0();
    __syncthreads();

    const int kb_lo = max(0, q0 - (WIN - 1)) >> 5;
    const int kb_hi = (q0 + 127) >> 5;
    const int qw_lo = q0 + w * 16;
    const int gq_row = lane >> 2;
    const int t4 = lane & 3;

    for (int kb = kb_lo; kb <= kb_hi; kb++) {
        const int k0 = kb * KT;
        __syncthreads();

        {
            const __half* gkh = Kh + (size_t)k0 * KVN + kvh * DH;
            const __half* gkl = Kl + (size_t)k0 * KVN + kvh * DH;
            const __half* gvh = Vh + (size_t)k0 * KVN + kvh * DH;
#pragma unroll
            for (int it = 0; it < 4; it++) {
                int id = t + it * 256;
                int row = id >> 5, ch = id & 31;
                uint32_t d = (uint32_t)(row * ASTR + ch * 8) * 2;
                size_t g = (size_t)row * KVN + ch * 8;
                CP16(sKh + d, gkh + g);
                CP16(sKl + d, gkl + g);
                CP16(sVh + d, gvh + g);
            }
        }
        CP_COMMIT();
        CP_WAIT0();
        __syncthreads();

        bool active = (k0 <= qw_lo + 15) && (k0 + KT - 1 >= qw_lo - (WIN - 1));
        if (!active) continue;

        float s[4][4];
        uint32_t sl[4][2];
#pragma unroll
        for (int tl = 0; tl < 4; tl++) {
#pragma unroll
            for (int r = 0; r < 4; r++) s[tl][r] = 0.f;
            sl[tl][0] = 0u; sl[tl][1] = 0u;
        }

#pragma unroll
        for (int dc = 0; dc < 16; dc++) {
            uint32_t qa[4], qb[4], k1h[4], k2h[4], k1l[4], k2l[4];
            uint32_t qoff = (uint32_t)((w * 16 + (lane & 15)) * ASTR + dc * 16 + (lane >> 4) * 8) * 2;
            LDSM4(qa, sQh + qoff);
            LDSM4(qb, sQl + qoff);
            uint32_t koff = (uint32_t)((lane & 15) * ASTR + dc * 16 + (lane >> 4) * 8) * 2;
            LDSM4(k1h, sKh + koff);
            LDSM4(k2h, sKh + koff + 16 * ASTR * 2);
            LDSM4(k1l, sKl + koff);
            LDSM4(k2l, sKl + koff + 16 * ASTR * 2);

            // hi pass (f32 acc)
            MMA_FP16(s[0], qa, k1h[0], k1h[2]);
            MMA_FP16(s[1], qa, k1h[1], k1h[3]);
            MMA_FP16(s[2], qa, k2h[0], k2h[2]);
            MMA_FP16(s[3], qa, k2h[1], k2h[3]);
            // cross passes (f16 acc)
            MMA_F16A(sl[0], qa, k1l[0], k1l[2]);
            MMA_F16A(sl[1], qa, k1l[1], k1l[3]);
            MMA_F16A(sl[2], qa, k2l[0], k2l[2]);
            MMA_F16A(sl[3], qa, k2l[1], k2l[3]);
            MMA_F16A(sl[0], qb, k1h[0], k1h[2]);
            MMA_F16A(sl[1], qb, k1h[1], k1h[3]);
            MMA_F16A(sl[2], qb, k2h[0], k2h[2]);
            MMA_F16A(sl[3], qb, k2h[1], k2h[3]);
        }
#pragma unroll
        for (int tl = 0; tl < 4; tl++) {
            add_h2(&s[tl][0], sl[tl][0]);
            add_h2(&s[tl][2], sl[tl][1]);
        }

        float corr[2];
#pragma unroll
        for (int r = 0; r < 2; r++) {
            int qg = qw_lo + gq_row + r * 8;
            float mx = -1e30f;
#pragma unroll
            for (int tl = 0; tl < 4; tl++) {
#pragma unroll
                for (int c = 0; c < 2; c++) {
                    int kg = k0 + tl * 8 + 2 * t4 + c;
                    bool ok = (kg <= qg) && (qg - kg < WIN);
                    if (!ok) s[tl][r * 2 + c] = -1e30f;
                    mx = fmaxf(mx, s[tl][r * 2 + c]);
                }
            }
            mx = fmaxf(mx, __shfl_xor_sync(0xffffffffu, mx, 1));
            mx = fmaxf(mx, __shfl_xor_sync(0xffffffffu, mx, 2));
            float m_new = fmaxf(mrow[r], mx);
            float mexp = (m_new <= -1e29f) ? 0.f : m_new;
            float sum = 0.f;
#pragma unroll
            for (int tl = 0; tl < 4; tl++) {
#pragma unroll
                for (int c = 0; c < 2; c++) {
                    float p = __expf(s[tl][r * 2 + c] - mexp);
                    s[tl][r * 2 + c] = p;
                    sum += p;
                }
            }
            sum += __shfl_xor_sync(0xffffffffu, sum, 1);
            sum += __shfl_xor_sync(0xffffffffu, sum, 2);
            corr[r] = __expf(mrow[r] - m_new);
            mrow[r] = m_new;
            lrow[r] = lrow[r] * corr[r] + sum;
        }

        uint32_t ph[2][4], pl[2][4];
#pragma unroll
        for (int kc = 0; kc < 2; kc++) {
#pragma unroll
            for (int r2 = 0; r2 < 4; r2++) {
                int tl = kc * 2 + (r2 >> 1);
                int r  = r2 & 1;
                float p0 = s[tl][r * 2 + 0];
                float p1 = s[tl][r * 2 + 1];
                __half h0 = __float2half_rn(p0);
                __half h1 = __float2half_rn(p1);
                __half2 hh = __halves2half2(h0, h1);
                __half2 ll = __halves2half2(__float2half_rn(p0 - __half2float(h0)),
                                            __float2half_rn(p1 - __half2float(h1)));
                ph[kc][r2] = *(uint32_t*)&hh;
                pl[kc][r2] = *(uint32_t*)&ll;
            }
        }

#pragma unroll
        for (int dt = 0; dt < 32; dt++) {
            o[dt][0] *= corr[0]; o[dt][1] *= corr[0];
            o[dt][2] *= corr[1]; o[dt][3] *= corr[1];
        }

#pragma unroll
        for (int dg = 0; dg < 16; dg++) {
#pragma unroll
            for (int kc = 0; kc < 2; kc++) {
                uint32_t vh4[4];
                uint32_t voff = (uint32_t)((kc * 16 + (lane & 7) + ((lane >> 3) & 1) * 8) * ASTR
                                           + dg * 16 + ((lane >> 4) & 1) * 8) * 2;
                LDSM4T(vh4, sVh + voff);
                MMA_FP16(o[2 * dg],     ph[kc], vh4[0], vh4[1]);
                MMA_FP16(o[2 * dg + 1], ph[kc], vh4[2], vh4[3]);
                MMA_FP16(o[2 * dg],     pl[kc], vh4[0], vh4[1]);
                MMA_FP16(o[2 * dg + 1], pl[kc], vh4[2], vh4[3]);
            }
        }
    }

    float inv0 = 1.f / lrow[0];
    float inv1 = 1.f / lrow[1];
    size_t r0 = (size_t)(q0 + w * 16 + gq_row) * QN + h * DH;
    size_t r1 = r0 + (size_t)8 * QN;
#pragma unroll
    for (int dt = 0; dt < 32; dt++) {
        int col = dt * 8 + 2 * t4;
        float a0 = o[dt][0] * inv0, a1 = o[dt][1] * inv0;
        float b0 = o[dt][2] * inv1, b1 = o[dt][3] * inv1;
        __half ha0 = __float2half_rn(a0), ha1 = __float2half_rn(a1);
        __half hb0 = __float2half_rn(b0), hb1 = __float2half_rn(b1);
        *(__half2*)(Oh + r0 + col) = __halves2half2(ha0, ha1);
        *(__half2*)(Oh + r1 + col) = __halves2half2(hb0, hb1);
        *(__half2*)(Ol + r0 + col) = __halves2half2(
            __float2half_rn(a0 - __half2float(ha0)), __float2half_rn(a1 - __half2float(ha1)));
        *(__half2*)(Ol + r1 + col) = __halves2half2(
            __float2half_rn(b0 - __half2float(hb0)), __float2half_rn(b1 - __half2float(hb1)));
    }
}

// =====================================================================
// kernel_launch
// =====================================================================
extern "C" void kernel_launch(void* const* d_in, const int* in_sizes, int n_in,
                              void* d_out, int out_size)
{
    const float* hs   = (const float*)d_in[0];
    const float* cosp = (const float*)d_in[1];
    const float* sinp = (const float*)d_in[2];
    const float* wq   = (const float*)d_in[3];
    const float* wk   = (const float*)d_in[4];
    const float* wv   = (const float*)d_in[5];
    const float* wo   = (const float*)d_in[6];
    const float* qw   = (const float*)d_in[7];
    const float* kw   = (const float*)d_in[8];
    float* out = (float*)d_out;

    float *gq, *gk, *gv;
    cudaGetSymbolAddress((void**)&gq, g_q);
    cudaGetSymbolAddress((void**)&gk, g_k);
    cudaGetSymbolAddress((void**)&gv, g_v);

    __half *hsh, *hsl, *wqh, *wql, *wkh, *wkl, *wvh, *woh, *ath, *atl;
    __half *qh, *ql, *kh, *kl, *vh;
    cudaGetSymbolAddress((void**)&hsh, g_hs_h); cudaGetSymbolAddress((void**)&hsl, g_hs_l);
    cudaGetSymbolAddress((void**)&wqh, g_wq_h); cudaGetSymbolAddress((void**)&wql, g_wq_l);
    cudaGetSymbolAddress((void**)&wkh, g_wk_h); cudaGetSymbolAddress((void**)&wkl, g_wk_l);
    cudaGetSymbolAddress((void**)&wvh, g_wv_h);
    cudaGetSymbolAddress((void**)&woh, g_wo_h);
    cudaGetSymbolAddress((void**)&ath, g_at_h); cudaGetSymbolAddress((void**)&atl, g_at_l);
    cudaGetSymbolAddress((void**)&qh, g_qh);    cudaGetSymbolAddress((void**)&ql, g_ql);
    cudaGetSymbolAddress((void**)&kh, g_kh);    cudaGetSymbolAddress((void**)&kl, g_kl);
    cudaGetSymbolAddress((void**)&vh, g_vh);

    cudaFuncSetAttribute(gemm3_kernel<3>, cudaFuncAttributeMaxDynamicSharedMemorySize,
                         GEMM_SMEM_BYTES);
    cudaFuncSetAttribute(gemm3_kernel<2>, cudaFuncAttributeMaxDynamicSharedMemorySize,
                         GEMM_SMEM_BYTES);
    cudaFuncSetAttribute(attn_tc_kernel, cudaFuncAttributeMaxDynamicSharedMemorySize,
                         ATT_SM_BYTES);

    // splits
    split_kernel<<<(S * HID / 4 + 255) / 256, 256>>>(hs, hsh, hsl, S * HID);
    split_kernel<<<(HID * QN / 4 + 255) / 256, 256>>>(wq, wqh, wql, HID * QN);
    split_kernel<<<(HID * KVN / 4 + 255) / 256, 256>>>(wk, wkh, wkl, HID * KVN);
    splith_kernel<<<(HID * KVN / 4 + 255) / 256, 256>>>(wv, wvh, HID * KVN);
    splith_kernel<<<(QN * HID / 4 + 255) / 256, 256>>>(wo, woh, QN * HID);

    // projections
    gemm3_kernel<3><<<dim3(QN / 128,  S / 128), 256, GEMM_SMEM_BYTES>>>(
        hsh, hsl, wqh, wql, gq, S, QN, HID);
    gemm3_kernel<3><<<dim3(KVN / 128, S / 128), 256, GEMM_SMEM_BYTES>>>(
        hsh, hsl, wkh, wkl, gk, S, KVN, HID);
    gemm3_kernel<2><<<dim3(KVN / 128, S / 128), 256, GEMM_SMEM_BYTES>>>(
        hsh, hsl, wvh, wvh, gv, S, KVN, HID);

    // RMSNorm + RoPE (warp-per-head)
    norm_rope_kernel<<<S * 16 / 8, 256>>>(gq, gk, gv, cosp, sinp, qw, kw,
                                          qh, ql, kh, kl, vh);

    // attention
    attn_tc_kernel<<<dim3(S / 128, NH), 256, ATT_SM_BYTES>>>(
        qh, ql, kh, kl, vh, ath, atl);

    // output projection
    gemm3_kernel<2><<<dim3(HID / 128, S / 128), 256, GEMM_SMEM_BYTES>>>(
        ath, atl, woh, woh, out, S, HID, QN);
}